// round 6
// baseline (speedup 1.0000x reference)
#include <cuda_runtime.h>
#include <math.h>
#include <stdint.h>

#define TOKENS 4096
#define HID    4096
#define NHEADS 32
#define NKVH   8
#define HDIM   128
#define SEQ    1024
#define QKV_LD 6144   // q(4096) | k(1024) | v(1024)

__device__ float g_qkv[TOKENS * QKV_LD];
__device__ float g_attn[TOKENS * HID];

// ---------------------------------------------------------------------------
// Helpers (mma.sync path — tcgen05 unavailable: harness PTX target is plain
// sm_103; all tcgen05 features are 'a'-gated)
// ---------------------------------------------------------------------------
__device__ __forceinline__ uint32_t smem_u32(const void* p) {
    uint32_t a;
    asm("{ .reg .u64 t; cvta.to.shared.u64 t, %1; cvt.u32.u64 %0, t; }"
        : "=r"(a) : "l"(p));
    return a;
}
__device__ __forceinline__ unsigned f2tf(float x) {
    unsigned r;
    asm("cvt.rna.tf32.f32 %0, %1;" : "=r"(r) : "f"(x));
    return r;
}
__device__ __forceinline__ void mma_tf32(float c[4],
    unsigned a0, unsigned a1, unsigned a2, unsigned a3,
    unsigned b0, unsigned b1) {
    asm volatile(
        "mma.sync.aligned.m16n8k8.row.col.f32.tf32.tf32.f32 "
        "{%0,%1,%2,%3}, {%4,%5,%6,%7}, {%8,%9}, {%0,%1,%2,%3};"
        : "+f"(c[0]), "+f"(c[1]), "+f"(c[2]), "+f"(c[3])
        : "r"(a0), "r"(a1), "r"(a2), "r"(a3), "r"(b0), "r"(b1));
}
__device__ __forceinline__ void cp16(uint32_t d, const void* s) {
    asm volatile("cp.async.cg.shared.global [%0], [%1], 16;" :: "r"(d), "l"(s));
}
#define CP_COMMIT() asm volatile("cp.async.commit_group;" ::: "memory")
#define CP_WAIT2()  asm volatile("cp.async.wait_group 2;" ::: "memory")

// ---------------------------------------------------------------------------
// TF32 GEMM: C[bm:bm+128, 0:256] = A[M,K] @ Bt[256,K]^T
// CTA 128x256, BK=16, 512 threads = 16 warps (2m x 8n), warp tile 64x32.
// 4-stage cp.async pipeline (raw fp32 in smem, cvt.rna.tf32 at gather).
// Smem row stride 20 words: conflict-free STS and gathers (proven r2/4/5).
// ---------------------------------------------------------------------------
#define SST   20
#define ASTG  (128 * SST)                 // words per A stage
#define BSTG  (256 * SST)                 // words per B stage
#define STGW  (ASTG + BSTG)               // 7680 words = 30 KB
#define KT    (HID / 16)                  // 256 iters
#define GSMEM (4 * STGW * 4)              // 120 KB

__device__ __forceinline__ void gemm256(
    const float* __restrict__ A, const float* __restrict__ Bt,
    float* __restrict__ C, int ldc, int bm)
{
    extern __shared__ float smg[];

    const int tid  = threadIdx.x;
    const int wid  = tid >> 5;
    const int lane = tid & 31;
    const int g    = lane >> 2;
    const int t    = lane & 3;
    const int wm   = (wid & 1) * 64;      // 2 m-warps
    const int wn   = (wid >> 1) * 32;     // 8 n-warps
    const int lr   = tid >> 2;            // 0..127 load row
    const int lc   = (tid & 3) * 4;       // k-chunk (floats)

    const uint32_t sb   = smem_u32(smg);
    const uint32_t adst = sb + (uint32_t)(lr * SST + lc) * 4u;
    const uint32_t bdst = adst + ASTG * 4u;

    const float* asrc = A  + (size_t)(bm + lr) * HID + lc;
    const float* bsrc = Bt + (size_t)lr * HID + lc;

#define ISSUE(S, KI) do { \
    const float* a_ = asrc + (KI) * 16; \
    const float* b_ = bsrc + (KI) * 16; \
    const uint32_t so_ = (uint32_t)(S) * (STGW * 4u); \
    cp16(adst + so_,               a_); \
    cp16(bdst + so_,               b_); \
    cp16(bdst + so_ + 128u*SST*4u, b_ + (size_t)128 * HID); \
} while (0)

    float acc[4][4][4];
#pragma unroll
    for (int i = 0; i < 4; i++)
#pragma unroll
        for (int j = 0; j < 4; j++)
#pragma unroll
            for (int r = 0; r < 4; r++) acc[i][j][r] = 0.f;

    // Prologue: fill 3 stages
    ISSUE(0, 0); CP_COMMIT();
    ISSUE(1, 1); CP_COMMIT();
    ISSUE(2, 2); CP_COMMIT();

    for (int i = 0; i < KT; i++) {
        CP_WAIT2();            // stage i's group complete (this thread)
        __syncthreads();       // all threads' cp.asyncs for stage i visible

        if (i + 3 < KT) ISSUE((i + 3) & 3, i + 3);
        CP_COMMIT();           // one group per iter keeps wait counting uniform

        const float* as = smg + (i & 3) * STGW;
        const float* bs = as + ASTG;
#pragma unroll
        for (int ks = 0; ks < 2; ks++) {
            const int kb = ks * 8;
            unsigned af[4][4], bf[4][2];
#pragma unroll
            for (int mi = 0; mi < 4; mi++) {
                const float* ap = as + (wm + mi * 16 + g) * SST + kb + t;
                af[mi][0] = f2tf(ap[0]);
                af[mi][1] = f2tf(ap[8 * SST]);
                af[mi][2] = f2tf(ap[4]);
                af[mi][3] = f2tf(ap[8 * SST + 4]);
            }
#pragma unroll
            for (int ni = 0; ni < 4; ni++) {
                const float* bp = bs + (wn + ni * 8 + g) * SST + kb + t;
                bf[ni][0] = f2tf(bp[0]);
                bf[ni][1] = f2tf(bp[4]);
            }
#pragma unroll
            for (int mi = 0; mi < 4; mi++)
#pragma unroll
                for (int ni = 0; ni < 4; ni++)
                    mma_tf32(acc[mi][ni], af[mi][0], af[mi][1], af[mi][2], af[mi][3],
                             bf[ni][0], bf[ni][1]);
        }
    }
#undef ISSUE

    // Epilogue
#pragma unroll
    for (int mi = 0; mi < 4; mi++) {
#pragma unroll
        for (int ni = 0; ni < 4; ni++) {
            float* cp = C + (size_t)(bm + wm + mi * 16 + g) * ldc + wn + ni * 8 + 2 * t;
            *(float2*)cp             = make_float2(acc[mi][ni][0], acc[mi][ni][1]);
            *(float2*)(cp + 8 * ldc) = make_float2(acc[mi][ni][2], acc[mi][ni][3]);
        }
    }
}

// grid.x = 24 n-tiles (16 q | 4 k | 4 v), grid.y = 32 m-tiles
__global__ __launch_bounds__(512, 1)
void qkv_gemm(const float* __restrict__ x, const float* __restrict__ wq,
              const float* __restrict__ wk, const float* __restrict__ wv,
              float* __restrict__ qkv) {
    const int nt = blockIdx.x;
    const float* B;
    if (nt < 16)      B = wq + (size_t)nt * 256 * HID;
    else if (nt < 20) B = wk + (size_t)(nt - 16) * 256 * HID;
    else              B = wv + (size_t)(nt - 20) * 256 * HID;
    gemm256(x, B, qkv + nt * 256, QKV_LD, blockIdx.y * 128);
}

// grid.x = 16 n-tiles, grid.y = 32 m-tiles
__global__ __launch_bounds__(512, 1)
void out_gemm(const float* __restrict__ A, const float* __restrict__ wo,
              float* __restrict__ C) {
    gemm256(A, wo + (size_t)blockIdx.x * 256 * HID, C + blockIdx.x * 256,
            HID, blockIdx.y * 128);
}

// ---------------------------------------------------------------------------
// RoPE in-place on q (heads 0..31) and k (heads 32..39) of g_qkv.
// ---------------------------------------------------------------------------
__global__ void rope_kernel(float* __restrict__ qkv,
                            const int* __restrict__ positions) {
    int idx = blockIdx.x * blockDim.x + threadIdx.x;
    const int total = TOKENS * (NHEADS + NKVH) * 64;
    if (idx >= total) return;
    int d = idx & 63;
    int rest = idx >> 6;
    int head = rest % (NHEADS + NKVH);
    int t = rest / (NHEADS + NKVH);

    int pos = positions[t];
    pos = pos < 0 ? 0 : (pos > SEQ - 1 ? SEQ - 1 : pos);

    float* base = qkv + (size_t)t * QKV_LD +
                  (head < NHEADS ? head * HDIM : HID + (head - NHEADS) * HDIM);
    float x1 = base[d];
    float x2 = base[d + 64];

    const float LC = 0.14391156831212875f;   // ln(10000)/64
    int j1 = d >> 1;
    float f1 = expf(-(float)j1 * LC);
    float f2 = expf(-(float)(j1 + 32) * LC);
    float p = (float)pos;
    float s1, c1, s2, c2;
    sincosf(p * f1, &s1, &c1);
    sincosf(p * f2, &s2, &c2);

    base[d]      = x1 * c1 - x2 * s1;
    base[d + 64] = x2 * c2 + x1 * s2;
}

// ---------------------------------------------------------------------------
// Flash attention (fp32, causal, GQA) — unchanged (next round's target).
// ---------------------------------------------------------------------------
#define ATT_SMEM ((3 * 64 * 128 + 64 * 65) * 4)

__device__ __forceinline__ int swz(int row, int k4) {
    return row * 32 + ((k4 & 24) | ((k4 ^ (row >> 2)) & 7));
}

__global__ __launch_bounds__(256)
void attn_kernel(const float* __restrict__ qkv, float* __restrict__ aout) {
    extern __shared__ float smem[];
    float4* Qs = (float4*)smem;
    float4* Ks = Qs + 64 * 32;
    float4* Vs = Ks + 64 * 32;
    float*  Ps = (float*)(Vs + 64 * 32);

    const int qb = blockIdx.x;
    const int h  = blockIdx.y;
    const int b  = blockIdx.z;
    const int kvh = h >> 2;
    const int tid = threadIdx.x;
    const int tx = tid & 15;
    const int ty = tid >> 4;
    const int q0 = qb * 64;
    const size_t tok0 = (size_t)b * SEQ;

    const float* qbase = qkv + (tok0 + q0) * QKV_LD + h * HDIM;
    for (int u = tid; u < 64 * 32; u += 256) {
        int r = u >> 5, k4 = u & 31;
        Qs[swz(r, k4)] = *(const float4*)(qbase + (size_t)r * QKV_LD + k4 * 4);
    }

    float m[4], l[4], o[4][8];
#pragma unroll
    for (int i = 0; i < 4; i++) {
        m[i] = -INFINITY; l[i] = 0.f;
#pragma unroll
        for (int j = 0; j < 8; j++) o[i][j] = 0.f;
    }

    const float* kbase = qkv + tok0 * QKV_LD + HID + kvh * HDIM;
    const float* vbase = kbase + NKVH * HDIM;

    for (int kb = 0; kb <= qb; kb++) {
        const int k0 = kb * 64;
        __syncthreads();
        for (int u = tid; u < 64 * 32; u += 256) {
            int r = u >> 5, k4 = u & 31;
            size_t roff = (size_t)(k0 + r) * QKV_LD + (size_t)k4 * 4;
            Ks[swz(r, k4)] = *(const float4*)(kbase + roff);
            Vs[u]          = *(const float4*)(vbase + roff);
        }
        __syncthreads();

        float s[4][4];
#pragma unroll
        for (int i = 0; i < 4; i++)
#pragma unroll
            for (int j = 0; j < 4; j++) s[i][j] = 0.f;

#pragma unroll 4
        for (int k4 = 0; k4 < 32; k4++) {
            float4 qv[4], kv[4];
#pragma unroll
            for (int i = 0; i < 4; i++)
                qv[i] = Qs[(ty * 4 + i) * 32 + ((k4 & 24) | ((k4 ^ ty) & 7))];
#pragma unroll
            for (int j = 0; j < 4; j++)
                kv[j] = Ks[(tx * 4 + j) * 32 + ((k4 & 24) | ((k4 ^ tx) & 7))];
#pragma unroll
            for (int i = 0; i < 4; i++)
#pragma unroll
                for (int j = 0; j < 4; j++)
                    s[i][j] += qv[i].x * kv[j].x + qv[i].y * kv[j].y +
                               qv[i].z * kv[j].z + qv[i].w * kv[j].w;
        }

        const float sc = 0.08838834764831845f;
#pragma unroll
        for (int i = 0; i < 4; i++) {
            const int qpos = q0 + ty * 4 + i;
            float rowm = -INFINITY;
#pragma unroll
            for (int j = 0; j < 4; j++) {
                float v = s[i][j] * sc;
                if (k0 + tx * 4 + j > qpos) v = -INFINITY;
                s[i][j] = v;
                rowm = fmaxf(rowm, v);
            }
#pragma unroll
            for (int off = 8; off; off >>= 1)
                rowm = fmaxf(rowm, __shfl_xor_sync(0xffffffffu, rowm, off));
            float nm = fmaxf(m[i], rowm);
            float corr = expf(m[i] - nm);
            float rs = 0.f;
#pragma unroll
            for (int j = 0; j < 4; j++) {
                float p = expf(s[i][j] - nm);
                Ps[(ty * 4 + i) * 65 + tx * 4 + j] = p;
                rs += p;
            }
#pragma unroll
            for (int off = 8; off; off >>= 1)
                rs += __shfl_xor_sync(0xffffffffu, rs, off);
            l[i] = l[i] * corr + rs;
            m[i] = nm;
#pragma unroll
            for (int j = 0; j < 8; j++) o[i][j] *= corr;
        }
        __syncthreads();

#pragma unroll 4
        for (int kk = 0; kk < 64; kk++) {
            float4 v1 = Vs[kk * 32 + tx];
            float4 v2 = Vs[kk * 32 + 16 + tx];
#pragma unroll
            for (int i = 0; i < 4; i++) {
                float p = Ps[(ty * 4 + i) * 65 + kk];
                o[i][0] += p * v1.x; o[i][1] += p * v1.y;
                o[i][2] += p * v1.z; o[i][3] += p * v1.w;
                o[i][4] += p * v2.x; o[i][5] += p * v2.y;
                o[i][6] += p * v2.z; o[i][7] += p * v2.w;
            }
        }
    }

    float* ob = aout + (tok0 + q0) * HID + h * HDIM;
#pragma unroll
    for (int i = 0; i < 4; i++) {
        int r = ty * 4 + i;
        float inv = 1.0f / l[i];
        float4 w1 = make_float4(o[i][0] * inv, o[i][1] * inv,
                                o[i][2] * inv, o[i][3] * inv);
        float4 w2 = make_float4(o[i][4] * inv, o[i][5] * inv,
                                o[i][6] * inv, o[i][7] * inv);
        *(float4*)(ob + (size_t)r * HID + tx * 4) = w1;
        *(float4*)(ob + (size_t)r * HID + 64 + tx * 4) = w2;
    }
}

// ---------------------------------------------------------------------------
// Launch
// ---------------------------------------------------------------------------
extern "C" void kernel_launch(void* const* d_in, const int* in_sizes, int n_in,
                              void* d_out, int out_size) {
    const float* x         = (const float*)d_in[0];
    const int*   positions = (const int*)d_in[1];
    const float* wq        = (const float*)d_in[3];
    const float* wk        = (const float*)d_in[4];
    const float* wv        = (const float*)d_in[5];
    const float* wo        = (const float*)d_in[6];
    float* out = (float*)d_out;

    float *qkv = nullptr, *attn = nullptr;
    cudaGetSymbolAddress((void**)&qkv, g_qkv);
    cudaGetSymbolAddress((void**)&attn, g_attn);

    cudaFuncSetAttribute(qkv_gemm, cudaFuncAttributeMaxDynamicSharedMemorySize, GSMEM);
    cudaFuncSetAttribute(out_gemm, cudaFuncAttributeMaxDynamicSharedMemorySize, GSMEM);
    cudaFuncSetAttribute(attn_kernel, cudaFuncAttributeMaxDynamicSharedMemorySize, ATT_SMEM);

    // QKV projection (tf32 HMMA, 512 threads, cp.async 4-stage pipeline)
    qkv_gemm<<<dim3(24, 32), 512, GSMEM>>>(x, wq, wk, wv, qkv);

    // RoPE on q and k
    rope_kernel<<<(TOKENS * 40 * 64 + 255) / 256, 256>>>(qkv, positions);

    // Flash attention (fp32)
    attn_kernel<<<dim3(SEQ / 64, NHEADS, TOKENS / SEQ), 256, ATT_SMEM>>>(qkv, attn);

    // Output projection (tf32 HMMA, 512 threads, cp.async 4-stage pipeline)
    out_gemm<<<dim3(16, 32), 512, GSMEM>>>(attn, wo, out);
}

// round 8
// speedup vs baseline: 1.2350x; 1.2350x over previous
#include <cuda_runtime.h>
#include <math.h>
#include <stdint.h>

#define TOKENS 4096
#define HID    4096
#define NHEADS 32
#define NKVH   8
#define HDIM   128
#define SEQ    1024
#define QKV_LD 6144   // q(4096) | k(1024) | v(1024)

__device__ float g_qkv[TOKENS * QKV_LD];
__device__ float g_attn[TOKENS * HID];

// ---------------------------------------------------------------------------
// Helpers (mma.sync path — tcgen05 unavailable on this toolchain)
// ---------------------------------------------------------------------------
__device__ __forceinline__ uint32_t smem_u32(const void* p) {
    uint32_t a;
    asm("{ .reg .u64 t; cvta.to.shared.u64 t, %1; cvt.u32.u64 %0, t; }"
        : "=r"(a) : "l"(p));
    return a;
}
__device__ __forceinline__ unsigned f2tf(float x) {
    unsigned r;
    asm("cvt.rna.tf32.f32 %0, %1;" : "=r"(r) : "f"(x));
    return r;
}
__device__ __forceinline__ void mma_tf32(float c[4],
    unsigned a0, unsigned a1, unsigned a2, unsigned a3,
    unsigned b0, unsigned b1) {
    asm volatile(
        "mma.sync.aligned.m16n8k8.row.col.f32.tf32.tf32.f32 "
        "{%0,%1,%2,%3}, {%4,%5,%6,%7}, {%8,%9}, {%0,%1,%2,%3};"
        : "+f"(c[0]), "+f"(c[1]), "+f"(c[2]), "+f"(c[3])
        : "r"(a0), "r"(a1), "r"(a2), "r"(a3), "r"(b0), "r"(b1));
}
__device__ __forceinline__ void cp16(uint32_t d, const void* s) {
    asm volatile("cp.async.cg.shared.global [%0], [%1], 16;" :: "r"(d), "l"(s));
}
#define CP_COMMIT() asm volatile("cp.async.commit_group;" ::: "memory")
#define CP_WAIT2()  asm volatile("cp.async.wait_group 2;" ::: "memory")

// ---------------------------------------------------------------------------
// TF32 GEMM (round-5 proven config): C[bm:bm+128, 0:256] = A @ Bt^T
// 256 threads, 8 warps (2m x 4n), warp tile 64x64, 4-stage cp.async, SST=20.
// ---------------------------------------------------------------------------
#define SST   20
#define ASTG  (128 * SST)
#define BSTG  (256 * SST)
#define STGW  (ASTG + BSTG)               // 30 KB
#define KT    (HID / 16)
#define GSMEM (4 * STGW * 4)              // 120 KB

__device__ __forceinline__ void gemm256(
    const float* __restrict__ A, const float* __restrict__ Bt,
    float* __restrict__ C, int ldc, int bm)
{
    extern __shared__ float smg[];

    const int tid  = threadIdx.x;
    const int wid  = tid >> 5;
    const int lane = tid & 31;
    const int g    = lane >> 2;
    const int t    = lane & 3;
    const int wm   = (wid & 1) * 64;
    const int wn   = (wid >> 1) * 64;
    const int lr   = tid >> 2;
    const int lc   = (tid & 3) * 4;

    const uint32_t sb   = smem_u32(smg);
    const uint32_t adst = sb + (uint32_t)(lr * SST + lc) * 4u;
    const uint32_t bdst = adst + ASTG * 4u;

    const float* asrc = A  + (size_t)(bm + lr) * HID + lc;
    const float* bsrc = Bt + (size_t)lr * HID + lc;

#define ISSUE(S, KI) do { \
    const float* a_ = asrc + (KI) * 16; \
    const float* b_ = bsrc + (KI) * 16; \
    const uint32_t so_ = (uint32_t)(S) * (STGW * 4u); \
    cp16(adst + so_,               a_); \
    cp16(adst + so_ + 64u*SST*4u,  a_ + (size_t)64 * HID); \
    cp16(bdst + so_,               b_); \
    cp16(bdst + so_ + 64u*SST*4u,  b_ + (size_t)64 * HID); \
    cp16(bdst + so_ + 128u*SST*4u, b_ + (size_t)128 * HID); \
    cp16(bdst + so_ + 192u*SST*4u, b_ + (size_t)192 * HID); \
} while (0)

    float acc[4][8][4];
#pragma unroll
    for (int i = 0; i < 4; i++)
#pragma unroll
        for (int j = 0; j < 8; j++)
#pragma unroll
            for (int r = 0; r < 4; r++) acc[i][j][r] = 0.f;

    ISSUE(0, 0); CP_COMMIT();
    ISSUE(1, 1); CP_COMMIT();
    ISSUE(2, 2); CP_COMMIT();

    for (int i = 0; i < KT; i++) {
        CP_WAIT2();
        __syncthreads();

        if (i + 3 < KT) ISSUE((i + 3) & 3, i + 3);
        CP_COMMIT();

        const float* as = smg + (i & 3) * STGW;
        const float* bs = as + ASTG;
#pragma unroll
        for (int ks = 0; ks < 2; ks++) {
            const int kb = ks * 8;
            unsigned af[4][4], bf[8][2];
#pragma unroll
            for (int mi = 0; mi < 4; mi++) {
                const float* ap = as + (wm + mi * 16 + g) * SST + kb + t;
                af[mi][0] = f2tf(ap[0]);
                af[mi][1] = f2tf(ap[8 * SST]);
                af[mi][2] = f2tf(ap[4]);
                af[mi][3] = f2tf(ap[8 * SST + 4]);
            }
#pragma unroll
            for (int ni = 0; ni < 8; ni++) {
                const float* bp = bs + (wn + ni * 8 + g) * SST + kb + t;
                bf[ni][0] = f2tf(bp[0]);
                bf[ni][1] = f2tf(bp[4]);
            }
#pragma unroll
            for (int mi = 0; mi < 4; mi++)
#pragma unroll
                for (int ni = 0; ni < 8; ni++)
                    mma_tf32(acc[mi][ni], af[mi][0], af[mi][1], af[mi][2], af[mi][3],
                             bf[ni][0], bf[ni][1]);
        }
    }
#undef ISSUE

#pragma unroll
    for (int mi = 0; mi < 4; mi++) {
#pragma unroll
        for (int ni = 0; ni < 8; ni++) {
            float* cp = C + (size_t)(bm + wm + mi * 16 + g) * ldc + wn + ni * 8 + 2 * t;
            *(float2*)cp             = make_float2(acc[mi][ni][0], acc[mi][ni][1]);
            *(float2*)(cp + 8 * ldc) = make_float2(acc[mi][ni][2], acc[mi][ni][3]);
        }
    }
}

__global__ __launch_bounds__(256, 1)
void qkv_gemm(const float* __restrict__ x, const float* __restrict__ wq,
              const float* __restrict__ wk, const float* __restrict__ wv,
              float* __restrict__ qkv) {
    const int nt = blockIdx.x;
    const float* B;
    if (nt < 16)      B = wq + (size_t)nt * 256 * HID;
    else if (nt < 20) B = wk + (size_t)(nt - 16) * 256 * HID;
    else              B = wv + (size_t)(nt - 20) * 256 * HID;
    gemm256(x, B, qkv + nt * 256, QKV_LD, blockIdx.y * 128);
}

__global__ __launch_bounds__(256, 1)
void out_gemm(const float* __restrict__ A, const float* __restrict__ wo,
              float* __restrict__ C) {
    gemm256(A, wo + (size_t)blockIdx.x * 256 * HID, C + blockIdx.x * 256,
            HID, blockIdx.y * 128);
}

// ---------------------------------------------------------------------------
// RoPE in-place on q (heads 0..31) and k (heads 32..39) of g_qkv.
// ---------------------------------------------------------------------------
__global__ void rope_kernel(float* __restrict__ qkv,
                            const int* __restrict__ positions) {
    int idx = blockIdx.x * blockDim.x + threadIdx.x;
    const int total = TOKENS * (NHEADS + NKVH) * 64;
    if (idx >= total) return;
    int d = idx & 63;
    int rest = idx >> 6;
    int head = rest % (NHEADS + NKVH);
    int t = rest / (NHEADS + NKVH);

    int pos = positions[t];
    pos = pos < 0 ? 0 : (pos > SEQ - 1 ? SEQ - 1 : pos);

    float* base = qkv + (size_t)t * QKV_LD +
                  (head < NHEADS ? head * HDIM : HID + (head - NHEADS) * HDIM);
    float x1 = base[d];
    float x2 = base[d + 64];

    const float LC = 0.14391156831212875f;   // ln(10000)/64
    int j1 = d >> 1;
    float f1 = expf(-(float)j1 * LC);
    float f2 = expf(-(float)(j1 + 32) * LC);
    float p = (float)pos;
    float s1, c1, s2, c2;
    sincosf(p * f1, &s1, &c1);
    sincosf(p * f2, &s2, &c2);

    base[d]      = x1 * c1 - x2 * s1;
    base[d + 64] = x2 * c2 + x1 * s2;
}

// ---------------------------------------------------------------------------
// Tensor-core flash attention (tf32 mma, causal, GQA).
// CTA: 128 queries x 1 head, 256 threads = 8 warps.
// EACH WARP OWNS 16 FULL ROWS (wm = wid*16): S warp tile 16x64 (K=128),
// PV warp tile 16x128 (K=64). P is warp-private -> no cross-warp softmax
// state, no CTA sync between softmax and PV.
// -inf guard: fully-masked rows use nm2=0 so exp() yields 0, never NaN.
// Strides: Q/K 132 (gather 4g+t), V 136 (gather 8t+g), P 68 (gather 4g+t)
// -> all fragment gathers hit 32 distinct banks.
// ---------------------------------------------------------------------------
#define QST 132
#define KST 132
#define VST 136
#define PST 68
#define ATT_SMEM ((128*QST + 64*KST + 64*VST + 128*PST) * 4)   // ~167 KB

__global__ __launch_bounds__(256, 1)
void attn_tc(const float* __restrict__ qkv, float* __restrict__ aout) {
    extern __shared__ float sm[];
    float* Qs = sm;
    float* Ks = Qs + 128 * QST;
    float* Vs = Ks + 64 * KST;
    float* Ps = Vs + 64 * VST;

    const int qb = blockIdx.x;         // 0..7
    const int h  = blockIdx.y;
    const int b  = blockIdx.z;
    const int kvh = h >> 2;
    const int tid = threadIdx.x;
    const int wid = tid >> 5;
    const int lane = tid & 31;
    const int g = lane >> 2;
    const int t = lane & 3;
    const int wm = wid * 16;           // warp owns rows wm..wm+15
    const int q0 = qb * 128;
    const size_t tok0 = (size_t)b * SEQ;

    // Load Q tile (128 x 128)
    const float* qbase = qkv + (tok0 + q0) * QKV_LD + h * HDIM;
    for (int u = tid; u < 128 * 32; u += 256) {
        int r = u >> 5, c = (u & 31) * 4;
        *(float4*)(Qs + r * QST + c) =
            *(const float4*)(qbase + (size_t)r * QKV_LD + c);
    }

    float m[2], l[2], o[16][4];
    m[0] = m[1] = -INFINITY;
    l[0] = l[1] = 0.f;
#pragma unroll
    for (int nj = 0; nj < 16; nj++)
#pragma unroll
        for (int r = 0; r < 4; r++) o[nj][r] = 0.f;

    const float* kbase = qkv + tok0 * QKV_LD + HID + kvh * HDIM;
    const float* vbase = kbase + NKVH * HDIM;
    const int nkb = 2 * (qb + 1);

    for (int kb = 0; kb < nkb; kb++) {
        const int k0 = kb * 64;
        __syncthreads();   // previous tile's readers done before overwrite
        for (int u = tid; u < 64 * 32; u += 256) {
            int r = u >> 5, c = (u & 31) * 4;
            size_t roff = (size_t)(k0 + r) * QKV_LD + c;
            *(float4*)(Ks + r * KST + c) = *(const float4*)(kbase + roff);
            *(float4*)(Vs + r * VST + c) = *(const float4*)(vbase + roff);
        }
        __syncthreads();

        // causal early-out: whole warp tile masked
        if (k0 > q0 + wm + 15) continue;

        // ---- S = Q K^T (warp 16x64, K=128) ----
        float s[8][4];
#pragma unroll
        for (int ni = 0; ni < 8; ni++)
#pragma unroll
            for (int r = 0; r < 4; r++) s[ni][r] = 0.f;

#pragma unroll 4
        for (int kk = 0; kk < 16; kk++) {
            const int kc = kk * 8;
            const float* ap = Qs + (wm + g) * QST + kc + t;
            unsigned a0 = f2tf(ap[0]);
            unsigned a1 = f2tf(ap[8 * QST]);
            unsigned a2 = f2tf(ap[4]);
            unsigned a3 = f2tf(ap[8 * QST + 4]);
            unsigned bf[8][2];
#pragma unroll
            for (int ni = 0; ni < 8; ni++) {
                const float* bp = Ks + (ni * 8 + g) * KST + kc + t;
                bf[ni][0] = f2tf(bp[0]);
                bf[ni][1] = f2tf(bp[4]);
            }
#pragma unroll
            for (int ni = 0; ni < 8; ni++)
                mma_tf32(s[ni], a0, a1, a2, a3, bf[ni][0], bf[ni][1]);
        }

        // ---- online softmax (rows wm+g, wm+g+8; guard -inf) ----
        const float sc = 0.08838834764831845f;  // 1/sqrt(128)
#pragma unroll
        for (int h2 = 0; h2 < 2; h2++) {
            const int qpos = q0 + wm + g + h2 * 8;
            float rowm = -INFINITY;
#pragma unroll
            for (int ni = 0; ni < 8; ni++) {
#pragma unroll
                for (int cj = 0; cj < 2; cj++) {
                    float v = s[ni][h2 * 2 + cj] * sc;
                    if (k0 + ni * 8 + 2 * t + cj > qpos) v = -INFINITY;
                    s[ni][h2 * 2 + cj] = v;
                    rowm = fmaxf(rowm, v);
                }
            }
            rowm = fmaxf(rowm, __shfl_xor_sync(0xffffffffu, rowm, 1));
            rowm = fmaxf(rowm, __shfl_xor_sync(0xffffffffu, rowm, 2));
            float nm  = fmaxf(m[h2], rowm);
            float nm2 = (nm == -INFINITY) ? 0.f : nm;   // NaN guard
            float corr = __expf(m[h2] - nm2);
            float rs = 0.f;
            float* prow = Ps + (wm + g + h2 * 8) * PST;
#pragma unroll
            for (int ni = 0; ni < 8; ni++) {
                float p0 = __expf(s[ni][h2 * 2]     - nm2);
                float p1 = __expf(s[ni][h2 * 2 + 1] - nm2);
                rs += p0 + p1;
                *(float2*)(prow + ni * 8 + 2 * t) = make_float2(p0, p1);
            }
            rs += __shfl_xor_sync(0xffffffffu, rs, 1);
            rs += __shfl_xor_sync(0xffffffffu, rs, 2);
            l[h2] = l[h2] * corr + rs;
            m[h2] = nm;
#pragma unroll
            for (int nj = 0; nj < 16; nj++) {
                o[nj][h2 * 2]     *= corr;
                o[nj][h2 * 2 + 1] *= corr;
            }
        }
        __syncwarp();   // P visible within warp

        // ---- O += P V (warp 16x128, K=64) ----
#pragma unroll 2
        for (int kk = 0; kk < 8; kk++) {
            const int kc = kk * 8;
            const float* ap = Ps + (wm + g) * PST + kc + t;
            unsigned a0 = f2tf(ap[0]);
            unsigned a1 = f2tf(ap[8 * PST]);
            unsigned a2 = f2tf(ap[4]);
            unsigned a3 = f2tf(ap[8 * PST + 4]);
#pragma unroll
            for (int nj = 0; nj < 16; nj++) {
                const float* bp = Vs + (kc + t) * VST + nj * 8 + g;
                unsigned b0 = f2tf(bp[0]);
                unsigned b1 = f2tf(bp[4 * VST]);
                mma_tf32(o[nj], a0, a1, a2, a3, b0, b1);
            }
        }
    }

    // Epilogue
    float* ob = aout + (tok0 + q0) * HID + h * HDIM;
#pragma unroll
    for (int h2 = 0; h2 < 2; h2++) {
        const float inv = 1.0f / l[h2];
        const int row = wm + g + h2 * 8;
#pragma unroll
        for (int nj = 0; nj < 16; nj++) {
            *(float2*)(ob + (size_t)row * HID + nj * 8 + 2 * t) =
                make_float2(o[nj][h2 * 2] * inv, o[nj][h2 * 2 + 1] * inv);
        }
    }
}

// ---------------------------------------------------------------------------
// Launch
// ---------------------------------------------------------------------------
extern "C" void kernel_launch(void* const* d_in, const int* in_sizes, int n_in,
                              void* d_out, int out_size) {
    const float* x         = (const float*)d_in[0];
    const int*   positions = (const int*)d_in[1];
    const float* wq        = (const float*)d_in[3];
    const float* wk        = (const float*)d_in[4];
    const float* wv        = (const float*)d_in[5];
    const float* wo        = (const float*)d_in[6];
    float* out = (float*)d_out;

    float *qkv = nullptr, *attn = nullptr;
    cudaGetSymbolAddress((void**)&qkv, g_qkv);
    cudaGetSymbolAddress((void**)&attn, g_attn);

    cudaFuncSetAttribute(qkv_gemm, cudaFuncAttributeMaxDynamicSharedMemorySize, GSMEM);
    cudaFuncSetAttribute(out_gemm, cudaFuncAttributeMaxDynamicSharedMemorySize, GSMEM);
    cudaFuncSetAttribute(attn_tc,  cudaFuncAttributeMaxDynamicSharedMemorySize, ATT_SMEM);

    // QKV projection (tf32 HMMA, round-5 config)
    qkv_gemm<<<dim3(24, 32), 256, GSMEM>>>(x, wq, wk, wv, qkv);

    // RoPE on q and k
    rope_kernel<<<(TOKENS * 40 * 64 + 255) / 256, 256>>>(qkv, positions);

    // Flash attention (tf32 tensor cores, warp-owns-rows)
    attn_tc<<<dim3(SEQ / 128, NHEADS, TOKENS / SEQ), 256, ATT_SMEM>>>(qkv, attn);

    // Output projection (tf32 HMMA)
    out_gemm<<<dim3(16, 32), 256, GSMEM>>>(attn, wo, out);
}

// round 9
// speedup vs baseline: 1.3294x; 1.0765x over previous
#include <cuda_runtime.h>
#include <math.h>
#include <stdint.h>

#define TOKENS 4096
#define HID    4096
#define NHEADS 32
#define NKVH   8
#define HDIM   128
#define SEQ    1024
#define QKV_LD 6144   // q(4096) | k(1024) | v(1024)

__device__ float g_qkv[TOKENS * QKV_LD];
__device__ float g_attn[TOKENS * HID];

// ---------------------------------------------------------------------------
// Helpers (mma.sync path — tcgen05 unavailable on this toolchain)
// ---------------------------------------------------------------------------
__device__ __forceinline__ uint32_t smem_u32(const void* p) {
    uint32_t a;
    asm("{ .reg .u64 t; cvta.to.shared.u64 t, %1; cvt.u32.u64 %0, t; }"
        : "=r"(a) : "l"(p));
    return a;
}
__device__ __forceinline__ unsigned f2tf(float x) {
    unsigned r;
    asm("cvt.rna.tf32.f32 %0, %1;" : "=r"(r) : "f"(x));
    return r;
}
__device__ __forceinline__ void mma_tf32(float c[4],
    unsigned a0, unsigned a1, unsigned a2, unsigned a3,
    unsigned b0, unsigned b1) {
    asm volatile(
        "mma.sync.aligned.m16n8k8.row.col.f32.tf32.tf32.f32 "
        "{%0,%1,%2,%3}, {%4,%5,%6,%7}, {%8,%9}, {%0,%1,%2,%3};"
        : "+f"(c[0]), "+f"(c[1]), "+f"(c[2]), "+f"(c[3])
        : "r"(a0), "r"(a1), "r"(a2), "r"(a3), "r"(b0), "r"(b1));
}
__device__ __forceinline__ void cp16(uint32_t d, const void* s) {
    asm volatile("cp.async.cg.shared.global [%0], [%1], 16;" :: "r"(d), "l"(s));
}
#define CP_COMMIT() asm volatile("cp.async.commit_group;" ::: "memory")
#define CP_WAIT2()  asm volatile("cp.async.wait_group 2;" ::: "memory")

// ---------------------------------------------------------------------------
// TF32 GEMM: C[bm:bm+128, 0:128] = A @ Bt^T
// CTA tile 128x128, 128 threads = 4 warps (2m x 2n), warp tile 64x64
// (fragment path identical to the proven round-5 code). 4-stage cp.async,
// 80 KB smem, ~180 regs -> 2 CTAs/SM co-resident: one CTA's mma fills the
// other CTA's wait/barrier idle time.
// ---------------------------------------------------------------------------
#define SST   20
#define ASTG  (128 * SST)                 // A stage words
#define STGW  (2 * ASTG)                  // A+B stage words (20 KB)
#define KT    (HID / 16)                  // 256 iters
#define GSMEM (4 * STGW * 4)              // 80 KB

__device__ __forceinline__ void gemm128(
    const float* __restrict__ A, const float* __restrict__ Bt,
    float* __restrict__ C, int ldc, int bm)
{
    extern __shared__ float smg[];

    const int tid  = threadIdx.x;
    const int wid  = tid >> 5;
    const int lane = tid & 31;
    const int g    = lane >> 2;
    const int t    = lane & 3;
    const int wm   = (wid & 1) * 64;
    const int wn   = (wid >> 1) * 64;
    const int lr   = tid >> 2;            // 0..31 load row base
    const int lc   = (tid & 3) * 4;       // float col 0/4/8/12

    const uint32_t sb   = smem_u32(smg);
    const uint32_t adst = sb + (uint32_t)(lr * SST + lc) * 4u;
    const uint32_t bdst = adst + ASTG * 4u;

    const float* asrc = A  + (size_t)(bm + lr) * HID + lc;
    const float* bsrc = Bt + (size_t)lr * HID + lc;

#define ISSUE(S, KI) do { \
    const float* a_ = asrc + (KI) * 16; \
    const float* b_ = bsrc + (KI) * 16; \
    const uint32_t so_ = (uint32_t)(S) * (STGW * 4u); \
    cp16(adst + so_,               a_); \
    cp16(adst + so_ + 32u*SST*4u,  a_ + (size_t)32 * HID); \
    cp16(adst + so_ + 64u*SST*4u,  a_ + (size_t)64 * HID); \
    cp16(adst + so_ + 96u*SST*4u,  a_ + (size_t)96 * HID); \
    cp16(bdst + so_,               b_); \
    cp16(bdst + so_ + 32u*SST*4u,  b_ + (size_t)32 * HID); \
    cp16(bdst + so_ + 64u*SST*4u,  b_ + (size_t)64 * HID); \
    cp16(bdst + so_ + 96u*SST*4u,  b_ + (size_t)96 * HID); \
} while (0)

    float acc[4][8][4];
#pragma unroll
    for (int i = 0; i < 4; i++)
#pragma unroll
        for (int j = 0; j < 8; j++)
#pragma unroll
            for (int r = 0; r < 4; r++) acc[i][j][r] = 0.f;

    ISSUE(0, 0); CP_COMMIT();
    ISSUE(1, 1); CP_COMMIT();
    ISSUE(2, 2); CP_COMMIT();

    for (int i = 0; i < KT; i++) {
        CP_WAIT2();
        __syncthreads();

        if (i + 3 < KT) ISSUE((i + 3) & 3, i + 3);
        CP_COMMIT();

        const float* as = smg + (i & 3) * STGW;
        const float* bs = as + ASTG;
#pragma unroll
        for (int ks = 0; ks < 2; ks++) {
            const int kb = ks * 8;
            unsigned af[4][4], bf[8][2];
#pragma unroll
            for (int mi = 0; mi < 4; mi++) {
                const float* ap = as + (wm + mi * 16 + g) * SST + kb + t;
                af[mi][0] = f2tf(ap[0]);
                af[mi][1] = f2tf(ap[8 * SST]);
                af[mi][2] = f2tf(ap[4]);
                af[mi][3] = f2tf(ap[8 * SST + 4]);
            }
#pragma unroll
            for (int ni = 0; ni < 8; ni++) {
                const float* bp = bs + (wn + ni * 8 + g) * SST + kb + t;
                bf[ni][0] = f2tf(bp[0]);
                bf[ni][1] = f2tf(bp[4]);
            }
#pragma unroll
            for (int mi = 0; mi < 4; mi++)
#pragma unroll
                for (int ni = 0; ni < 8; ni++)
                    mma_tf32(acc[mi][ni], af[mi][0], af[mi][1], af[mi][2], af[mi][3],
                             bf[ni][0], bf[ni][1]);
        }
    }
#undef ISSUE

#pragma unroll
    for (int mi = 0; mi < 4; mi++) {
#pragma unroll
        for (int ni = 0; ni < 8; ni++) {
            float* cp = C + (size_t)(bm + wm + mi * 16 + g) * ldc + wn + ni * 8 + 2 * t;
            *(float2*)cp             = make_float2(acc[mi][ni][0], acc[mi][ni][1]);
            *(float2*)(cp + 8 * ldc) = make_float2(acc[mi][ni][2], acc[mi][ni][3]);
        }
    }
}

// grid.x = 48 n-tiles (32 q | 8 k | 8 v), grid.y = 32 m-tiles
__global__ __launch_bounds__(128, 2)
void qkv_gemm(const float* __restrict__ x, const float* __restrict__ wq,
              const float* __restrict__ wk, const float* __restrict__ wv,
              float* __restrict__ qkv) {
    const int nt = blockIdx.x;
    const float* B;
    if (nt < 32)      B = wq + (size_t)nt * 128 * HID;
    else if (nt < 40) B = wk + (size_t)(nt - 32) * 128 * HID;
    else              B = wv + (size_t)(nt - 40) * 128 * HID;
    gemm128(x, B, qkv + nt * 128, QKV_LD, blockIdx.y * 128);
}

// grid.x = 32 n-tiles, grid.y = 32 m-tiles
__global__ __launch_bounds__(128, 2)
void out_gemm(const float* __restrict__ A, const float* __restrict__ wo,
              float* __restrict__ C) {
    gemm128(A, wo + (size_t)blockIdx.x * 128 * HID, C + blockIdx.x * 128,
            HID, blockIdx.y * 128);
}

// ---------------------------------------------------------------------------
// RoPE in-place on q (heads 0..31) and k (heads 32..39) of g_qkv.
// ---------------------------------------------------------------------------
__global__ void rope_kernel(float* __restrict__ qkv,
                            const int* __restrict__ positions) {
    int idx = blockIdx.x * blockDim.x + threadIdx.x;
    const int total = TOKENS * (NHEADS + NKVH) * 64;
    if (idx >= total) return;
    int d = idx & 63;
    int rest = idx >> 6;
    int head = rest % (NHEADS + NKVH);
    int t = rest / (NHEADS + NKVH);

    int pos = positions[t];
    pos = pos < 0 ? 0 : (pos > SEQ - 1 ? SEQ - 1 : pos);

    float* base = qkv + (size_t)t * QKV_LD +
                  (head < NHEADS ? head * HDIM : HID + (head - NHEADS) * HDIM);
    float x1 = base[d];
    float x2 = base[d + 64];

    const float LC = 0.14391156831212875f;   // ln(10000)/64
    int j1 = d >> 1;
    float f1 = expf(-(float)j1 * LC);
    float f2 = expf(-(float)(j1 + 32) * LC);
    float p = (float)pos;
    float s1, c1, s2, c2;
    sincosf(p * f1, &s1, &c1);
    sincosf(p * f2, &s2, &c2);

    base[d]      = x1 * c1 - x2 * s1;
    base[d + 64] = x2 * c2 + x1 * s2;
}

// ---------------------------------------------------------------------------
// Tensor-core flash attention (tf32 mma, causal, GQA) — round-8 proven.
// ---------------------------------------------------------------------------
#define QST 132
#define KST 132
#define VST 136
#define PST 68
#define ATT_SMEM ((128*QST + 64*KST + 64*VST + 128*PST) * 4)   // ~167 KB

__global__ __launch_bounds__(256, 1)
void attn_tc(const float* __restrict__ qkv, float* __restrict__ aout) {
    extern __shared__ float sm[];
    float* Qs = sm;
    float* Ks = Qs + 128 * QST;
    float* Vs = Ks + 64 * KST;
    float* Ps = Vs + 64 * VST;

    const int qb = blockIdx.x;
    const int h  = blockIdx.y;
    const int b  = blockIdx.z;
    const int kvh = h >> 2;
    const int tid = threadIdx.x;
    const int wid = tid >> 5;
    const int lane = tid & 31;
    const int g = lane >> 2;
    const int t = lane & 3;
    const int wm = wid * 16;
    const int q0 = qb * 128;
    const size_t tok0 = (size_t)b * SEQ;

    const float* qbase = qkv + (tok0 + q0) * QKV_LD + h * HDIM;
    for (int u = tid; u < 128 * 32; u += 256) {
        int r = u >> 5, c = (u & 31) * 4;
        *(float4*)(Qs + r * QST + c) =
            *(const float4*)(qbase + (size_t)r * QKV_LD + c);
    }

    float m[2], l[2], o[16][4];
    m[0] = m[1] = -INFINITY;
    l[0] = l[1] = 0.f;
#pragma unroll
    for (int nj = 0; nj < 16; nj++)
#pragma unroll
        for (int r = 0; r < 4; r++) o[nj][r] = 0.f;

    const float* kbase = qkv + tok0 * QKV_LD + HID + kvh * HDIM;
    const float* vbase = kbase + NKVH * HDIM;
    const int nkb = 2 * (qb + 1);

    for (int kb = 0; kb < nkb; kb++) {
        const int k0 = kb * 64;
        __syncthreads();
        for (int u = tid; u < 64 * 32; u += 256) {
            int r = u >> 5, c = (u & 31) * 4;
            size_t roff = (size_t)(k0 + r) * QKV_LD + c;
            *(float4*)(Ks + r * KST + c) = *(const float4*)(kbase + roff);
            *(float4*)(Vs + r * VST + c) = *(const float4*)(vbase + roff);
        }
        __syncthreads();

        if (k0 > q0 + wm + 15) continue;

        float s[8][4];
#pragma unroll
        for (int ni = 0; ni < 8; ni++)
#pragma unroll
            for (int r = 0; r < 4; r++) s[ni][r] = 0.f;

#pragma unroll 4
        for (int kk = 0; kk < 16; kk++) {
            const int kc = kk * 8;
            const float* ap = Qs + (wm + g) * QST + kc + t;
            unsigned a0 = f2tf(ap[0]);
            unsigned a1 = f2tf(ap[8 * QST]);
            unsigned a2 = f2tf(ap[4]);
            unsigned a3 = f2tf(ap[8 * QST + 4]);
            unsigned bf[8][2];
#pragma unroll
            for (int ni = 0; ni < 8; ni++) {
                const float* bp = Ks + (ni * 8 + g) * KST + kc + t;
                bf[ni][0] = f2tf(bp[0]);
                bf[ni][1] = f2tf(bp[4]);
            }
#pragma unroll
            for (int ni = 0; ni < 8; ni++)
                mma_tf32(s[ni], a0, a1, a2, a3, bf[ni][0], bf[ni][1]);
        }

        const float sc = 0.08838834764831845f;
#pragma unroll
        for (int h2 = 0; h2 < 2; h2++) {
            const int qpos = q0 + wm + g + h2 * 8;
            float rowm = -INFINITY;
#pragma unroll
            for (int ni = 0; ni < 8; ni++) {
#pragma unroll
                for (int cj = 0; cj < 2; cj++) {
                    float v = s[ni][h2 * 2 + cj] * sc;
                    if (k0 + ni * 8 + 2 * t + cj > qpos) v = -INFINITY;
                    s[ni][h2 * 2 + cj] = v;
                    rowm = fmaxf(rowm, v);
                }
            }
            rowm = fmaxf(rowm, __shfl_xor_sync(0xffffffffu, rowm, 1));
            rowm = fmaxf(rowm, __shfl_xor_sync(0xffffffffu, rowm, 2));
            float nm  = fmaxf(m[h2], rowm);
            float nm2 = (nm == -INFINITY) ? 0.f : nm;   // NaN guard
            float corr = __expf(m[h2] - nm2);
            float rs = 0.f;
            float* prow = Ps + (wm + g + h2 * 8) * PST;
#pragma unroll
            for (int ni = 0; ni < 8; ni++) {
                float p0 = __expf(s[ni][h2 * 2]     - nm2);
                float p1 = __expf(s[ni][h2 * 2 + 1] - nm2);
                rs += p0 + p1;
                *(float2*)(prow + ni * 8 + 2 * t) = make_float2(p0, p1);
            }
            rs += __shfl_xor_sync(0xffffffffu, rs, 1);
            rs += __shfl_xor_sync(0xffffffffu, rs, 2);
            l[h2] = l[h2] * corr + rs;
            m[h2] = nm;
#pragma unroll
            for (int nj = 0; nj < 16; nj++) {
                o[nj][h2 * 2]     *= corr;
                o[nj][h2 * 2 + 1] *= corr;
            }
        }
        __syncwarp();

#pragma unroll 2
        for (int kk = 0; kk < 8; kk++) {
            const int kc = kk * 8;
            const float* ap = Ps + (wm + g) * PST + kc + t;
            unsigned a0 = f2tf(ap[0]);
            unsigned a1 = f2tf(ap[8 * PST]);
            unsigned a2 = f2tf(ap[4]);
            unsigned a3 = f2tf(ap[8 * PST + 4]);
#pragma unroll
            for (int nj = 0; nj < 16; nj++) {
                const float* bp = Vs + (kc + t) * VST + nj * 8 + g;
                unsigned b0 = f2tf(bp[0]);
                unsigned b1 = f2tf(bp[4 * VST]);
                mma_tf32(o[nj], a0, a1, a2, a3, b0, b1);
            }
        }
    }

    float* ob = aout + (tok0 + q0) * HID + h * HDIM;
#pragma unroll
    for (int h2 = 0; h2 < 2; h2++) {
        const float inv = 1.0f / l[h2];
        const int row = wm + g + h2 * 8;
#pragma unroll
        for (int nj = 0; nj < 16; nj++) {
            *(float2*)(ob + (size_t)row * HID + nj * 8 + 2 * t) =
                make_float2(o[nj][h2 * 2] * inv, o[nj][h2 * 2 + 1] * inv);
        }
    }
}

// ---------------------------------------------------------------------------
// Launch
// ---------------------------------------------------------------------------
extern "C" void kernel_launch(void* const* d_in, const int* in_sizes, int n_in,
                              void* d_out, int out_size) {
    const float* x         = (const float*)d_in[0];
    const int*   positions = (const int*)d_in[1];
    const float* wq        = (const float*)d_in[3];
    const float* wk        = (const float*)d_in[4];
    const float* wv        = (const float*)d_in[5];
    const float* wo        = (const float*)d_in[6];
    float* out = (float*)d_out;

    float *qkv = nullptr, *attn = nullptr;
    cudaGetSymbolAddress((void**)&qkv, g_qkv);
    cudaGetSymbolAddress((void**)&attn, g_attn);

    cudaFuncSetAttribute(qkv_gemm, cudaFuncAttributeMaxDynamicSharedMemorySize, GSMEM);
    cudaFuncSetAttribute(out_gemm, cudaFuncAttributeMaxDynamicSharedMemorySize, GSMEM);
    cudaFuncSetAttribute(attn_tc,  cudaFuncAttributeMaxDynamicSharedMemorySize, ATT_SMEM);

    // QKV projection (tf32 HMMA, 128x128 CTAs, 2 CTAs/SM)
    qkv_gemm<<<dim3(48, 32), 128, GSMEM>>>(x, wq, wk, wv, qkv);

    // RoPE on q and k
    rope_kernel<<<(TOKENS * 40 * 64 + 255) / 256, 256>>>(qkv, positions);

    // Flash attention (tf32 tensor cores, warp-owns-rows)
    attn_tc<<<dim3(SEQ / 128, NHEADS, TOKENS / SEQ), 256, ATT_SMEM>>>(qkv, attn);

    // Output projection (tf32 HMMA, 128x128 CTAs, 2 CTAs/SM)
    out_gemm<<<dim3(32, 32), 128, GSMEM>>>(attn, wo, out);
}

// round 11
// speedup vs baseline: 2.3381x; 1.7588x over previous
#include <cuda_runtime.h>
#include <cuda_fp16.h>
#include <math.h>
#include <stdint.h>

#define TOKENS 4096
#define HID    4096
#define NHEADS 32
#define NKVH   8
#define HDIM   128
#define SEQ    1024
#define QKV_LD 6144   // q(4096) | k(1024) | v(1024)

// Scratch (__device__ globals; allocation-free rule)
__device__ float  g_qkv[TOKENS * QKV_LD];          // fp32 qkv (rope + attn input)
__device__ __half g_xh[TOKENS * HID];              // x in fp16
__device__ __half g_wh[10240 * HID];               // wq|wk|wv|wo in fp16 (4096+1024+1024+4096 rows)
__device__ __half g_attnh[TOKENS * HID];           // attention output in fp16
#define WQ_OFF 0
#define WK_OFF (4096 * 4096)
#define WV_OFF (WK_OFF + 1024 * 4096)
#define WO_OFF (WV_OFF + 1024 * 4096)               // ends at 10240*4096: fits

// ---------------------------------------------------------------------------
// Helpers
// ---------------------------------------------------------------------------
__device__ __forceinline__ uint32_t smem_u32(const void* p) {
    uint32_t a;
    asm("{ .reg .u64 t; cvta.to.shared.u64 t, %1; cvt.u32.u64 %0, t; }"
        : "=r"(a) : "l"(p));
    return a;
}
__device__ __forceinline__ unsigned f2tf(float x) {
    unsigned r;
    asm("cvt.rna.tf32.f32 %0, %1;" : "=r"(r) : "f"(x));
    return r;
}
__device__ __forceinline__ void mma_tf32(float c[4],
    unsigned a0, unsigned a1, unsigned a2, unsigned a3,
    unsigned b0, unsigned b1) {
    asm volatile(
        "mma.sync.aligned.m16n8k8.row.col.f32.tf32.tf32.f32 "
        "{%0,%1,%2,%3}, {%4,%5,%6,%7}, {%8,%9}, {%0,%1,%2,%3};"
        : "+f"(c[0]), "+f"(c[1]), "+f"(c[2]), "+f"(c[3])
        : "r"(a0), "r"(a1), "r"(a2), "r"(a3), "r"(b0), "r"(b1));
}
__device__ __forceinline__ void mma_f16(float c[4],
    unsigned a0, unsigned a1, unsigned a2, unsigned a3,
    unsigned b0, unsigned b1) {
    asm volatile(
        "mma.sync.aligned.m16n8k16.row.col.f32.f16.f16.f32 "
        "{%0,%1,%2,%3}, {%4,%5,%6,%7}, {%8,%9}, {%0,%1,%2,%3};"
        : "+f"(c[0]), "+f"(c[1]), "+f"(c[2]), "+f"(c[3])
        : "r"(a0), "r"(a1), "r"(a2), "r"(a3), "r"(b0), "r"(b1));
}
__device__ __forceinline__ void cp16(uint32_t d, const void* s) {
    asm volatile("cp.async.cg.shared.global [%0], [%1], 16;" :: "r"(d), "l"(s));
}
#define CP_COMMIT() asm volatile("cp.async.commit_group;" ::: "memory")
#define CP_WAIT2()  asm volatile("cp.async.wait_group 2;" ::: "memory")

// ---------------------------------------------------------------------------
// fp32 -> fp16 convert (vectorized)
// ---------------------------------------------------------------------------
__global__ void conv_f2h(const float* __restrict__ s, __half* __restrict__ d,
                         int n4) {
    int i = blockIdx.x * blockDim.x + threadIdx.x;
    if (i >= n4) return;
    float4 v = *(const float4*)(s + i * 4);
    __half2* dp = (__half2*)(d + i * 4);
    dp[0] = __floats2half2_rn(v.x, v.y);
    dp[1] = __floats2half2_rn(v.z, v.w);
}

// ---------------------------------------------------------------------------
// FP16 GEMM: C[bm:bm+128, 0:128] = A[M,4096] @ Bt[128,4096]^T  (fp16 in,
// fp32 accum/out). CTA 128x128, 128 threads = 4 warps (2m x 2n), warp 64x64.
// BK=32 (2 x k16 mma slabs per barrier), 4-stage cp.async, 80 KB smem,
// 2 CTAs/SM. Smem rows: 32 halves + 8 pad = 20 words -> the proven
// (rowstride mod 32 == 4) conflict-free gather pattern.
// ---------------------------------------------------------------------------
#define RSW   20                         // row stride, 4B words
#define ASTB  (128 * RSW * 4)            // A stage bytes (10240)
#define STGB  (2 * ASTB)                 // stage bytes   (20480)
#define KTH   (HID / 32)                 // 128 iters
#define GSMEM (4 * STGB)                 // 81920

__device__ __forceinline__ void gemm128h(
    const __half* __restrict__ A, const __half* __restrict__ Bt,
    float* __restrict__ C, int ldc, int bm)
{
    extern __shared__ float smg[];

    const int tid  = threadIdx.x;
    const int wid  = tid >> 5;
    const int lane = tid & 31;
    const int g    = lane >> 2;
    const int t    = lane & 3;
    const int wm   = (wid & 1) * 64;
    const int wn   = (wid >> 1) * 64;
    const int lr   = tid >> 2;            // 0..31 load row base
    const int lc8  = (tid & 3) * 8;       // half offset in row

    const uint32_t sb   = smem_u32(smg);
    const uint32_t adst = sb + (uint32_t)(lr * 80 + (tid & 3) * 16);
    const uint32_t bdst = adst + (uint32_t)ASTB;

    const __half* a0p = A  + (size_t)(bm + lr) * HID + lc8;
    const __half* b0p = Bt + (size_t)lr * HID + lc8;

#define ISSUE(S, KI) do { \
    const __half* a_ = a0p + (size_t)(KI) * 32; \
    const __half* b_ = b0p + (size_t)(KI) * 32; \
    const uint32_t so_ = (uint32_t)(S) * (uint32_t)STGB; \
    cp16(adst + so_,         a_); \
    cp16(adst + so_ + 2560u, a_ + (size_t)32 * HID); \
    cp16(adst + so_ + 5120u, a_ + (size_t)64 * HID); \
    cp16(adst + so_ + 7680u, a_ + (size_t)96 * HID); \
    cp16(bdst + so_,         b_); \
    cp16(bdst + so_ + 2560u, b_ + (size_t)32 * HID); \
    cp16(bdst + so_ + 5120u, b_ + (size_t)64 * HID); \
    cp16(bdst + so_ + 7680u, b_ + (size_t)96 * HID); \
} while (0)

    float acc[4][8][4];
#pragma unroll
    for (int i = 0; i < 4; i++)
#pragma unroll
        for (int j = 0; j < 8; j++)
#pragma unroll
            for (int r = 0; r < 4; r++) acc[i][j][r] = 0.f;

    ISSUE(0, 0); CP_COMMIT();
    ISSUE(1, 1); CP_COMMIT();
    ISSUE(2, 2); CP_COMMIT();

    for (int i = 0; i < KTH; i++) {
        CP_WAIT2();
        __syncthreads();

        if (i + 3 < KTH) ISSUE((i + 3) & 3, i + 3);
        CP_COMMIT();

        const uint32_t* as = (const uint32_t*)smg + (i & 3) * (STGB / 4);
        const uint32_t* bs = as + (ASTB / 4);
#pragma unroll
        for (int ks = 0; ks < 2; ks++) {
            const int kb = ks * 8;         // word offset of this k16 slab
            unsigned af[4][4], bf[8][2];
#pragma unroll
            for (int mi = 0; mi < 4; mi++) {
                const uint32_t* ap = as + (wm + mi * 16 + g) * RSW + kb + t;
                af[mi][0] = ap[0];
                af[mi][1] = ap[8 * RSW];
                af[mi][2] = ap[4];
                af[mi][3] = ap[8 * RSW + 4];
            }
#pragma unroll
            for (int ni = 0; ni < 8; ni++) {
                const uint32_t* bp = bs + (wn + ni * 8 + g) * RSW + kb + t;
                bf[ni][0] = bp[0];
                bf[ni][1] = bp[4];
            }
#pragma unroll
            for (int mi = 0; mi < 4; mi++)
#pragma unroll
                for (int ni = 0; ni < 8; ni++)
                    mma_f16(acc[mi][ni], af[mi][0], af[mi][1], af[mi][2], af[mi][3],
                            bf[ni][0], bf[ni][1]);
        }
    }
#undef ISSUE

#pragma unroll
    for (int mi = 0; mi < 4; mi++) {
#pragma unroll
        for (int ni = 0; ni < 8; ni++) {
            float* cp = C + (size_t)(bm + wm + mi * 16 + g) * ldc + wn + ni * 8 + 2 * t;
            *(float2*)cp             = make_float2(acc[mi][ni][0], acc[mi][ni][1]);
            *(float2*)(cp + 8 * ldc) = make_float2(acc[mi][ni][2], acc[mi][ni][3]);
        }
    }
}

// grid.x = 48 n-tiles (32 q | 8 k | 8 v), grid.y = 32 m-tiles
__global__ __launch_bounds__(128, 2)
void qkv_gemm(const __half* __restrict__ xh, const __half* __restrict__ wh,
              float* __restrict__ qkv) {
    const int nt = blockIdx.x;
    const __half* B;
    if (nt < 32)      B = wh + WQ_OFF + (size_t)nt * 128 * HID;
    else if (nt < 40) B = wh + WK_OFF + (size_t)(nt - 32) * 128 * HID;
    else              B = wh + WV_OFF + (size_t)(nt - 40) * 128 * HID;
    gemm128h(xh, B, qkv + nt * 128, QKV_LD, blockIdx.y * 128);
}

// grid.x = 32 n-tiles, grid.y = 32 m-tiles
__global__ __launch_bounds__(128, 2)
void out_gemm(const __half* __restrict__ ah, const __half* __restrict__ wh,
              float* __restrict__ C) {
    gemm128h(ah, wh + WO_OFF + (size_t)blockIdx.x * 128 * HID,
             C + blockIdx.x * 128, HID, blockIdx.y * 128);
}

// ---------------------------------------------------------------------------
// RoPE in-place on q (heads 0..31) and k (heads 32..39) of g_qkv.
// ---------------------------------------------------------------------------
__global__ void rope_kernel(float* __restrict__ qkv,
                            const int* __restrict__ positions) {
    int idx = blockIdx.x * blockDim.x + threadIdx.x;
    const int total = TOKENS * (NHEADS + NKVH) * 64;
    if (idx >= total) return;
    int d = idx & 63;
    int rest = idx >> 6;
    int head = rest % (NHEADS + NKVH);
    int t = rest / (NHEADS + NKVH);

    int pos = positions[t];
    pos = pos < 0 ? 0 : (pos > SEQ - 1 ? SEQ - 1 : pos);

    float* base = qkv + (size_t)t * QKV_LD +
                  (head < NHEADS ? head * HDIM : HID + (head - NHEADS) * HDIM);
    float x1 = base[d];
    float x2 = base[d + 64];

    const float LC = 0.14391156831212875f;   // ln(10000)/64
    int j1 = d >> 1;
    float f1 = expf(-(float)j1 * LC);
    float f2 = expf(-(float)(j1 + 32) * LC);
    float p = (float)pos;
    float s1, c1, s2, c2;
    sincosf(p * f1, &s1, &c1);
    sincosf(p * f2, &s2, &c2);

    base[d]      = x1 * c1 - x2 * s1;
    base[d + 64] = x2 * c2 + x1 * s2;
}

// ---------------------------------------------------------------------------
// Tensor-core flash attention (tf32 mma, causal, GQA) — round-8 proven.
// Output written directly in fp16 (feeds out_gemm's cp.async path).
// ---------------------------------------------------------------------------
#define QST 132
#define KST 132
#define VST 136
#define PST 68
#define ATT_SMEM ((128*QST + 64*KST + 64*VST + 128*PST) * 4)   // ~167 KB

__global__ __launch_bounds__(256, 1)
void attn_tc(const float* __restrict__ qkv, __half* __restrict__ aout) {
    extern __shared__ float sm[];
    float* Qs = sm;
    float* Ks = Qs + 128 * QST;
    float* Vs = Ks + 64 * KST;
    float* Ps = Vs + 64 * VST;

    const int qb = blockIdx.x;
    const int h  = blockIdx.y;
    const int b  = blockIdx.z;
    const int kvh = h >> 2;
    const int tid = threadIdx.x;
    const int wid = tid >> 5;
    const int lane = tid & 31;
    const int g = lane >> 2;
    const int t = lane & 3;
    const int wm = wid * 16;
    const int q0 = qb * 128;
    const size_t tok0 = (size_t)b * SEQ;

    const float* qbase = qkv + (tok0 + q0) * QKV_LD + h * HDIM;
    for (int u = tid; u < 128 * 32; u += 256) {
        int r = u >> 5, c = (u & 31) * 4;
        *(float4*)(Qs + r * QST + c) =
            *(const float4*)(qbase + (size_t)r * QKV_LD + c);
    }

    float m[2], l[2], o[16][4];
    m[0] = m[1] = -INFINITY;
    l[0] = l[1] = 0.f;
#pragma unroll
    for (int nj = 0; nj < 16; nj++)
#pragma unroll
        for (int r = 0; r < 4; r++) o[nj][r] = 0.f;

    const float* kbase = qkv + tok0 * QKV_LD + HID + kvh * HDIM;
    const float* vbase = kbase + NKVH * HDIM;
    const int nkb = 2 * (qb + 1);

    for (int kb = 0; kb < nkb; kb++) {
        const int k0 = kb * 64;
        __syncthreads();
        for (int u = tid; u < 64 * 32; u += 256) {
            int r = u >> 5, c = (u & 31) * 4;
            size_t roff = (size_t)(k0 + r) * QKV_LD + c;
            *(float4*)(Ks + r * KST + c) = *(const float4*)(kbase + roff);
            *(float4*)(Vs + r * VST + c) = *(const float4*)(vbase + roff);
        }
        __syncthreads();

        if (k0 > q0 + wm + 15) continue;

        float s[8][4];
#pragma unroll
        for (int ni = 0; ni < 8; ni++)
#pragma unroll
            for (int r = 0; r < 4; r++) s[ni][r] = 0.f;

#pragma unroll 4
        for (int kk = 0; kk < 16; kk++) {
            const int kc = kk * 8;
            const float* ap = Qs + (wm + g) * QST + kc + t;
            unsigned a0 = f2tf(ap[0]);
            unsigned a1 = f2tf(ap[8 * QST]);
            unsigned a2 = f2tf(ap[4]);
            unsigned a3 = f2tf(ap[8 * QST + 4]);
            unsigned bf[8][2];
#pragma unroll
            for (int ni = 0; ni < 8; ni++) {
                const float* bp = Ks + (ni * 8 + g) * KST + kc + t;
                bf[ni][0] = f2tf(bp[0]);
                bf[ni][1] = f2tf(bp[4]);
            }
#pragma unroll
            for (int ni = 0; ni < 8; ni++)
                mma_tf32(s[ni], a0, a1, a2, a3, bf[ni][0], bf[ni][1]);
        }

        const float sc = 0.08838834764831845f;
#pragma unroll
        for (int h2 = 0; h2 < 2; h2++) {
            const int qpos = q0 + wm + g + h2 * 8;
            float rowm = -INFINITY;
#pragma unroll
            for (int ni = 0; ni < 8; ni++) {
#pragma unroll
                for (int cj = 0; cj < 2; cj++) {
                    float v = s[ni][h2 * 2 + cj] * sc;
                    if (k0 + ni * 8 + 2 * t + cj > qpos) v = -INFINITY;
                    s[ni][h2 * 2 + cj] = v;
                    rowm = fmaxf(rowm, v);
                }
            }
            rowm = fmaxf(rowm, __shfl_xor_sync(0xffffffffu, rowm, 1));
            rowm = fmaxf(rowm, __shfl_xor_sync(0xffffffffu, rowm, 2));
            float nm  = fmaxf(m[h2], rowm);
            float nm2 = (nm == -INFINITY) ? 0.f : nm;   // NaN guard
            float corr = __expf(m[h2] - nm2);
            float rs = 0.f;
            float* prow = Ps + (wm + g + h2 * 8) * PST;
#pragma unroll
            for (int ni = 0; ni < 8; ni++) {
                float p0 = __expf(s[ni][h2 * 2]     - nm2);
                float p1 = __expf(s[ni][h2 * 2 + 1] - nm2);
                rs += p0 + p1;
                *(float2*)(prow + ni * 8 + 2 * t) = make_float2(p0, p1);
            }
            rs += __shfl_xor_sync(0xffffffffu, rs, 1);
            rs += __shfl_xor_sync(0xffffffffu, rs, 2);
            l[h2] = l[h2] * corr + rs;
            m[h2] = nm;
#pragma unroll
            for (int nj = 0; nj < 16; nj++) {
                o[nj][h2 * 2]     *= corr;
                o[nj][h2 * 2 + 1] *= corr;
            }
        }
        __syncwarp();

#pragma unroll 2
        for (int kk = 0; kk < 8; kk++) {
            const int kc = kk * 8;
            const float* ap = Ps + (wm + g) * PST + kc + t;
            unsigned a0 = f2tf(ap[0]);
            unsigned a1 = f2tf(ap[8 * PST]);
            unsigned a2 = f2tf(ap[4]);
            unsigned a3 = f2tf(ap[8 * PST + 4]);
#pragma unroll
            for (int nj = 0; nj < 16; nj++) {
                const float* bp = Vs + (kc + t) * VST + nj * 8 + g;
                unsigned b0 = f2tf(bp[0]);
                unsigned b1 = f2tf(bp[4 * VST]);
                mma_tf32(o[nj], a0, a1, a2, a3, b0, b1);
            }
        }
    }

    // Epilogue: write fp16 (out_gemm input)
    __half* ob = aout + (tok0 + q0) * HID + h * HDIM;
#pragma unroll
    for (int h2 = 0; h2 < 2; h2++) {
        const float inv = 1.0f / l[h2];
        const int row = wm + g + h2 * 8;
#pragma unroll
        for (int nj = 0; nj < 16; nj++) {
            *(__half2*)(ob + (size_t)row * HID + nj * 8 + 2 * t) =
                __floats2half2_rn(o[nj][h2 * 2] * inv, o[nj][h2 * 2 + 1] * inv);
        }
    }
}

// ---------------------------------------------------------------------------
// Launch
// ---------------------------------------------------------------------------
extern "C" void kernel_launch(void* const* d_in, const int* in_sizes, int n_in,
                              void* d_out, int out_size) {
    const float* x         = (const float*)d_in[0];
    const int*   positions = (const int*)d_in[1];
    const float* wq        = (const float*)d_in[3];
    const float* wk        = (const float*)d_in[4];
    const float* wv        = (const float*)d_in[5];
    const float* wo        = (const float*)d_in[6];
    float* out = (float*)d_out;

    float  *qkv = nullptr;
    __half *xh = nullptr, *wh = nullptr, *attnh = nullptr;
    cudaGetSymbolAddress((void**)&qkv,   g_qkv);
    cudaGetSymbolAddress((void**)&xh,    g_xh);
    cudaGetSymbolAddress((void**)&wh,    g_wh);
    cudaGetSymbolAddress((void**)&attnh, g_attnh);

    cudaFuncSetAttribute(qkv_gemm, cudaFuncAttributeMaxDynamicSharedMemorySize, GSMEM);
    cudaFuncSetAttribute(out_gemm, cudaFuncAttributeMaxDynamicSharedMemorySize, GSMEM);
    cudaFuncSetAttribute(attn_tc,  cudaFuncAttributeMaxDynamicSharedMemorySize, ATT_SMEM);

    // fp32 -> fp16 converts (x + weights)
    const int cb = 256;
    conv_f2h<<<(TOKENS * HID / 4 + cb - 1) / cb, cb>>>(x,  xh,          TOKENS * HID / 4);
    conv_f2h<<<(4096 * HID / 4 + cb - 1) / cb, cb>>>(wq, wh + WQ_OFF, 4096 * HID / 4);
    conv_f2h<<<(1024 * HID / 4 + cb - 1) / cb, cb>>>(wk, wh + WK_OFF, 1024 * HID / 4);
    conv_f2h<<<(1024 * HID / 4 + cb - 1) / cb, cb>>>(wv, wh + WV_OFF, 1024 * HID / 4);
    conv_f2h<<<(4096 * HID / 4 + cb - 1) / cb, cb>>>(wo, wh + WO_OFF, 4096 * HID / 4);

    // QKV projection (fp16 HMMA)
    qkv_gemm<<<dim3(48, 32), 128, GSMEM>>>(xh, wh, qkv);

    // RoPE on q and k (fp32)
    rope_kernel<<<(TOKENS * 40 * 64 + 255) / 256, 256>>>(qkv, positions);

    // Flash attention (tf32 tensor cores) -> fp16 output
    attn_tc<<<dim3(SEQ / 128, NHEADS, TOKENS / SEQ), 256, ATT_SMEM>>>(qkv, attnh);

    // Output projection (fp16 HMMA)
    out_gemm<<<dim3(32, 32), 128, GSMEM>>>(attnh, wh, out);
}

// round 13
// speedup vs baseline: 2.6382x; 1.1283x over previous
#include <cuda_runtime.h>
#include <cuda_fp16.h>
#include <math.h>
#include <stdint.h>

#define TOKENS 4096
#define HID    4096
#define NHEADS 32
#define NKVH   8
#define HDIM   128
#define SEQ    1024
#define QKV_LD 6144   // q(4096) | k(1024) | v(1024)
#define QK_LD  5120   // fp16 rope'd: q(4096) | k(1024)

// Scratch (__device__ globals; allocation-free rule)
__device__ float  g_qkv[TOKENS * QKV_LD];          // fp32 qkv (gemm out, rope/vt in)
__device__ __half g_xh[TOKENS * HID];              // x in fp16
__device__ __half g_wh[10240 * HID];               // wq|wk|wv|wo in fp16
__device__ __half g_attnh[TOKENS * HID];           // attention output in fp16
__device__ __half g_qkh[TOKENS * QK_LD];           // rope'd q|k in fp16
__device__ __half g_vt[4 * NKVH * HDIM * SEQ];     // V transposed [b][kvh][d][pos]
#define WQ_OFF 0
#define WK_OFF (4096 * 4096)
#define WV_OFF (WK_OFF + 1024 * 4096)
#define WO_OFF (WV_OFF + 1024 * 4096)

// ---------------------------------------------------------------------------
// Helpers
// ---------------------------------------------------------------------------
__device__ __forceinline__ uint32_t smem_u32(const void* p) {
    uint32_t a;
    asm("{ .reg .u64 t; cvta.to.shared.u64 t, %1; cvt.u32.u64 %0, t; }"
        : "=r"(a) : "l"(p));
    return a;
}
__device__ __forceinline__ void mma_f16(float c[4],
    unsigned a0, unsigned a1, unsigned a2, unsigned a3,
    unsigned b0, unsigned b1) {
    asm volatile(
        "mma.sync.aligned.m16n8k16.row.col.f32.f16.f16.f32 "
        "{%0,%1,%2,%3}, {%4,%5,%6,%7}, {%8,%9}, {%0,%1,%2,%3};"
        : "+f"(c[0]), "+f"(c[1]), "+f"(c[2]), "+f"(c[3])
        : "r"(a0), "r"(a1), "r"(a2), "r"(a3), "r"(b0), "r"(b1));
}
__device__ __forceinline__ void cp16(uint32_t d, const void* s) {
    asm volatile("cp.async.cg.shared.global [%0], [%1], 16;" :: "r"(d), "l"(s));
}
#define CP_COMMIT() asm volatile("cp.async.commit_group;" ::: "memory")
#define CP_WAIT2()  asm volatile("cp.async.wait_group 2;" ::: "memory")

// ---------------------------------------------------------------------------
// fp32 -> fp16 convert (vectorized)
// ---------------------------------------------------------------------------
__global__ void conv_f2h(const float* __restrict__ s, __half* __restrict__ d,
                         int n4) {
    int i = blockIdx.x * blockDim.x + threadIdx.x;
    if (i >= n4) return;
    float4 v = *(const float4*)(s + i * 4);
    __half2* dp = (__half2*)(d + i * 4);
    dp[0] = __floats2half2_rn(v.x, v.y);
    dp[1] = __floats2half2_rn(v.z, v.w);
}

// ---------------------------------------------------------------------------
// FP16 GEMM (round-11 proven): C[bm:bm+128, 0:128] = A @ Bt^T
// ---------------------------------------------------------------------------
#define RSW   20
#define ASTB  (128 * RSW * 4)            // 10240
#define STGB  (2 * ASTB)                 // 20480
#define KTH   (HID / 32)                 // 128
#define GSMEM (4 * STGB)                 // 81920

__device__ __forceinline__ void gemm128h(
    const __half* __restrict__ A, const __half* __restrict__ Bt,
    float* __restrict__ C, int ldc, int bm)
{
    extern __shared__ float smg[];

    const int tid  = threadIdx.x;
    const int wid  = tid >> 5;
    const int lane = tid & 31;
    const int g    = lane >> 2;
    const int t    = lane & 3;
    const int wm   = (wid & 1) * 64;
    const int wn   = (wid >> 1) * 64;
    const int lr   = tid >> 2;
    const int lc8  = (tid & 3) * 8;

    const uint32_t sb   = smem_u32(smg);
    const uint32_t adst = sb + (uint32_t)(lr * 80 + (tid & 3) * 16);
    const uint32_t bdst = adst + (uint32_t)ASTB;

    const __half* a0p = A  + (size_t)(bm + lr) * HID + lc8;
    const __half* b0p = Bt + (size_t)lr * HID + lc8;

#define ISSUE(S, KI) do { \
    const __half* a_ = a0p + (size_t)(KI) * 32; \
    const __half* b_ = b0p + (size_t)(KI) * 32; \
    const uint32_t so_ = (uint32_t)(S) * (uint32_t)STGB; \
    cp16(adst + so_,         a_); \
    cp16(adst + so_ + 2560u, a_ + (size_t)32 * HID); \
    cp16(adst + so_ + 5120u, a_ + (size_t)64 * HID); \
    cp16(adst + so_ + 7680u, a_ + (size_t)96 * HID); \
    cp16(bdst + so_,         b_); \
    cp16(bdst + so_ + 2560u, b_ + (size_t)32 * HID); \
    cp16(bdst + so_ + 5120u, b_ + (size_t)64 * HID); \
    cp16(bdst + so_ + 7680u, b_ + (size_t)96 * HID); \
} while (0)

    float acc[4][8][4];
#pragma unroll
    for (int i = 0; i < 4; i++)
#pragma unroll
        for (int j = 0; j < 8; j++)
#pragma unroll
            for (int r = 0; r < 4; r++) acc[i][j][r] = 0.f;

    ISSUE(0, 0); CP_COMMIT();
    ISSUE(1, 1); CP_COMMIT();
    ISSUE(2, 2); CP_COMMIT();

    for (int i = 0; i < KTH; i++) {
        CP_WAIT2();
        __syncthreads();

        if (i + 3 < KTH) ISSUE((i + 3) & 3, i + 3);
        CP_COMMIT();

        const uint32_t* as = (const uint32_t*)smg + (i & 3) * (STGB / 4);
        const uint32_t* bs = as + (ASTB / 4);
#pragma unroll
        for (int ks = 0; ks < 2; ks++) {
            const int kb = ks * 8;
            unsigned af[4][4], bf[8][2];
#pragma unroll
            for (int mi = 0; mi < 4; mi++) {
                const uint32_t* ap = as + (wm + mi * 16 + g) * RSW + kb + t;
                af[mi][0] = ap[0];
                af[mi][1] = ap[8 * RSW];
                af[mi][2] = ap[4];
                af[mi][3] = ap[8 * RSW + 4];
            }
#pragma unroll
            for (int ni = 0; ni < 8; ni++) {
                const uint32_t* bp = bs + (wn + ni * 8 + g) * RSW + kb + t;
                bf[ni][0] = bp[0];
                bf[ni][1] = bp[4];
            }
#pragma unroll
            for (int mi = 0; mi < 4; mi++)
#pragma unroll
                for (int ni = 0; ni < 8; ni++)
                    mma_f16(acc[mi][ni], af[mi][0], af[mi][1], af[mi][2], af[mi][3],
                            bf[ni][0], bf[ni][1]);
        }
    }
#undef ISSUE

#pragma unroll
    for (int mi = 0; mi < 4; mi++) {
#pragma unroll
        for (int ni = 0; ni < 8; ni++) {
            float* cp = C + (size_t)(bm + wm + mi * 16 + g) * ldc + wn + ni * 8 + 2 * t;
            *(float2*)cp             = make_float2(acc[mi][ni][0], acc[mi][ni][1]);
            *(float2*)(cp + 8 * ldc) = make_float2(acc[mi][ni][2], acc[mi][ni][3]);
        }
    }
}

__global__ __launch_bounds__(128, 2)
void qkv_gemm(const __half* __restrict__ xh, const __half* __restrict__ wh,
              float* __restrict__ qkv) {
    const int nt = blockIdx.x;
    const __half* B;
    if (nt < 32)      B = wh + WQ_OFF + (size_t)nt * 128 * HID;
    else if (nt < 40) B = wh + WK_OFF + (size_t)(nt - 32) * 128 * HID;
    else              B = wh + WV_OFF + (size_t)(nt - 40) * 128 * HID;
    gemm128h(xh, B, qkv + nt * 128, QKV_LD, blockIdx.y * 128);
}

__global__ __launch_bounds__(128, 2)
void out_gemm(const __half* __restrict__ ah, const __half* __restrict__ wh,
              float* __restrict__ C) {
    gemm128h(ah, wh + WO_OFF + (size_t)blockIdx.x * 128 * HID,
             C + blockIdx.x * 128, HID, blockIdx.y * 128);
}

// ---------------------------------------------------------------------------
// RoPE: read fp32 q/k from g_qkv, write fp16 into packed g_qkh.
// ---------------------------------------------------------------------------
__global__ void rope_h(const float* __restrict__ qkv,
                       const int* __restrict__ positions,
                       __half* __restrict__ qkh) {
    int idx = blockIdx.x * blockDim.x + threadIdx.x;
    const int total = TOKENS * (NHEADS + NKVH) * 64;
    if (idx >= total) return;
    int d = idx & 63;
    int rest = idx >> 6;
    int head = rest % (NHEADS + NKVH);
    int t = rest / (NHEADS + NKVH);

    int pos = positions[t];
    pos = pos < 0 ? 0 : (pos > SEQ - 1 ? SEQ - 1 : pos);

    const int off = (head < NHEADS) ? head * HDIM : HID + (head - NHEADS) * HDIM;
    const float* src = qkv + (size_t)t * QKV_LD + off;
    __half* dst = qkh + (size_t)t * QK_LD + off;
    float x1 = src[d];
    float x2 = src[d + 64];

    const float LC = 0.14391156831212875f;   // ln(10000)/64
    int j1 = d >> 1;
    float f1 = expf(-(float)j1 * LC);
    float f2 = expf(-(float)(j1 + 32) * LC);
    float p = (float)pos;
    float s1, c1, s2, c2;
    sincosf(p * f1, &s1, &c1);
    sincosf(p * f2, &s2, &c2);

    dst[d]      = __float2half(x1 * c1 - x2 * s1);
    dst[d + 64] = __float2half(x2 * c2 + x1 * s2);
}

// ---------------------------------------------------------------------------
// V transpose+convert: g_qkv v-region [tok][d] fp32 -> g_vt [b][kvh][d][pos] fp16.
// ---------------------------------------------------------------------------
__global__ void conv_vt(const float* __restrict__ qkv, __half* __restrict__ vt) {
    __shared__ float tile[32][33];
    const int bk = blockIdx.z;               // b*8 + kvh
    const int p0 = blockIdx.x * 32;
    const int d0 = blockIdx.y * 32;
    const int tx = threadIdx.x & 31;
    const int ty = threadIdx.x >> 5;         // 0..7
    const int b  = bk >> 3, kvh = bk & 7;

    const float* src = qkv + (size_t)(b * SEQ + p0) * QKV_LD + 5120 + kvh * HDIM + d0;
#pragma unroll
    for (int i = 0; i < 4; i++) {
        int r = ty + 8 * i;                   // pos within tile
        tile[r][tx] = src[(size_t)r * QKV_LD + tx];
    }
    __syncthreads();
    __half* dst = vt + ((size_t)bk * HDIM + d0) * SEQ + p0;
#pragma unroll
    for (int i = 0; i < 4; i++) {
        int r = ty + 8 * i;                   // d within tile
        dst[(size_t)r * SEQ + tx] = __float2half(tile[tx][r]);
    }
}

// ---------------------------------------------------------------------------
// FP16 tensor-core flash attention (causal, GQA).
// CTA: 128 q x 1 head, 256 thr = 8 warps, warp owns 16 full rows.
// FIXED vs round 12: uint4 = 4 words / 8 halves — tile loads now use
// 16 chunks/row (Q,K: 64 words) and 8 chunks/row (Vt: 32 words); no gaps.
// ---------------------------------------------------------------------------
#define AQW 68
#define AKW 68
#define AVW 36
#define APW 36
#define ATTW (128 * AQW + 64 * AKW + 128 * AVW + 128 * APW)   // 22272 words
#define ATT_SMEM (ATTW * 4)                                    // 89088 B

__global__ __launch_bounds__(256, 2)
void attn_h(const __half* __restrict__ qkh, const __half* __restrict__ vt,
            __half* __restrict__ aout) {
    extern __shared__ uint32_t smw[];
    uint32_t* Qs = smw;
    uint32_t* Ks = Qs + 128 * AQW;
    uint32_t* Vs = Ks + 64 * AKW;
    uint32_t* Ps = Vs + 128 * AVW;

    const int qb = blockIdx.x;
    const int h  = blockIdx.y;
    const int b  = blockIdx.z;
    const int kvh = h >> 2;
    const int tid = threadIdx.x;
    const int wid = tid >> 5;
    const int lane = tid & 31;
    const int g = lane >> 2;
    const int t = lane & 3;
    const int wm = wid * 16;
    const int q0 = qb * 128;
    const size_t tok0 = (size_t)b * SEQ;

    // Load Q tile: 128 rows x 64 words = 16 uint4 chunks/row
    const __half* qbase = qkh + (tok0 + q0) * QK_LD + h * HDIM;
    for (int u = tid; u < 128 * 16; u += 256) {
        int r = u >> 4, c = u & 15;
        *(uint4*)(Qs + r * AQW + c * 4) =
            *(const uint4*)(qbase + (size_t)r * QK_LD + c * 8);
    }

    float m[2], l[2], o[16][4];
    m[0] = m[1] = -INFINITY;
    l[0] = l[1] = 0.f;
#pragma unroll
    for (int nj = 0; nj < 16; nj++)
#pragma unroll
        for (int r = 0; r < 4; r++) o[nj][r] = 0.f;

    const __half* kbase = qkh + tok0 * QK_LD + HID + kvh * HDIM;
    const __half* vtb   = vt + (size_t)(b * NKVH + kvh) * HDIM * SEQ;
    const int nkb = 2 * (qb + 1);

    for (int kb = 0; kb < nkb; kb++) {
        const int k0 = kb * 64;
        __syncthreads();
        // K: 64 rows x 64 words = 16 chunks/row
        for (int u = tid; u < 64 * 16; u += 256) {
            int r = u >> 4, c = u & 15;
            *(uint4*)(Ks + r * AKW + c * 4) =
                *(const uint4*)(kbase + (size_t)(k0 + r) * QK_LD + c * 8);
        }
        // Vt: 128 rows x 32 words = 8 chunks/row
        for (int u = tid; u < 128 * 8; u += 256) {
            int r = u >> 3, c = u & 7;
            *(uint4*)(Vs + r * AVW + c * 4) =
                *(const uint4*)(vtb + (size_t)r * SEQ + k0 + c * 8);
        }
        __syncthreads();

        if (k0 > q0 + wm + 15) continue;   // causal early-out

        // ---- S = Q K^T (fp16 k16, 8 slabs) ----
        float s[8][4];
#pragma unroll
        for (int ni = 0; ni < 8; ni++)
#pragma unroll
            for (int r = 0; r < 4; r++) s[ni][r] = 0.f;

#pragma unroll
        for (int kk = 0; kk < 8; kk++) {
            const int kc = kk * 8;
            const uint32_t* ap = Qs + (wm + g) * AQW + kc + t;
            unsigned a0 = ap[0], a1 = ap[8 * AQW], a2 = ap[4], a3 = ap[8 * AQW + 4];
#pragma unroll
            for (int ni = 0; ni < 8; ni++) {
                const uint32_t* bp = Ks + (ni * 8 + g) * AKW + kc + t;
                mma_f16(s[ni], a0, a1, a2, a3, bp[0], bp[4]);
            }
        }

        // ---- online softmax (rows wm+g, wm+g+8) ----
        const float sc = 0.08838834764831845f;  // 1/sqrt(128)
#pragma unroll
        for (int h2 = 0; h2 < 2; h2++) {
            const int qpos = q0 + wm + g + h2 * 8;
            float rowm = -INFINITY;
#pragma unroll
            for (int ni = 0; ni < 8; ni++) {
#pragma unroll
                for (int cj = 0; cj < 2; cj++) {
                    float v = s[ni][h2 * 2 + cj] * sc;
                    if (k0 + ni * 8 + 2 * t + cj > qpos) v = -INFINITY;
                    s[ni][h2 * 2 + cj] = v;
                    rowm = fmaxf(rowm, v);
                }
            }
            rowm = fmaxf(rowm, __shfl_xor_sync(0xffffffffu, rowm, 1));
            rowm = fmaxf(rowm, __shfl_xor_sync(0xffffffffu, rowm, 2));
            float nm  = fmaxf(m[h2], rowm);
            float nm2 = (nm == -INFINITY) ? 0.f : nm;    // NaN guard
            float corr = __expf(m[h2] - nm2);
            float rs = 0.f;
            uint32_t* prow = Ps + (wm + g + h2 * 8) * APW;
#pragma unroll
            for (int ni = 0; ni < 8; ni++) {
                float p0 = __expf(s[ni][h2 * 2]     - nm2);
                float p1 = __expf(s[ni][h2 * 2 + 1] - nm2);
                rs += p0 + p1;
                *(__half2*)(prow + ni * 4 + t) = __floats2half2_rn(p0, p1);
            }
            rs += __shfl_xor_sync(0xffffffffu, rs, 1);
            rs += __shfl_xor_sync(0xffffffffu, rs, 2);
            l[h2] = l[h2] * corr + rs;
            m[h2] = nm;
#pragma unroll
            for (int nj = 0; nj < 16; nj++) {
                o[nj][h2 * 2]     *= corr;
                o[nj][h2 * 2 + 1] *= corr;
            }
        }
        __syncwarp();   // P visible within warp

        // ---- O += P V (fp16 k16, 4 slabs over 64 keys) ----
#pragma unroll
        for (int kk = 0; kk < 4; kk++) {
            const int kc = kk * 8;
            const uint32_t* ap = Ps + (wm + g) * APW + kc + t;
            unsigned a0 = ap[0], a1 = ap[8 * APW], a2 = ap[4], a3 = ap[8 * APW + 4];
#pragma unroll
            for (int nj = 0; nj < 16; nj++) {
                const uint32_t* bp = Vs + (nj * 8 + g) * AVW + kc + t;
                mma_f16(o[nj], a0, a1, a2, a3, bp[0], bp[4]);
            }
        }
    }

    // Epilogue: fp16 out (feeds out_gemm)
    __half* ob = aout + (tok0 + q0) * HID + h * HDIM;
#pragma unroll
    for (int h2 = 0; h2 < 2; h2++) {
        const float inv = 1.0f / l[h2];
        const int row = wm + g + h2 * 8;
#pragma unroll
        for (int nj = 0; nj < 16; nj++) {
            *(__half2*)(ob + (size_t)row * HID + nj * 8 + 2 * t) =
                __floats2half2_rn(o[nj][h2 * 2] * inv, o[nj][h2 * 2 + 1] * inv);
        }
    }
}

// ---------------------------------------------------------------------------
// Launch
// ---------------------------------------------------------------------------
extern "C" void kernel_launch(void* const* d_in, const int* in_sizes, int n_in,
                              void* d_out, int out_size) {
    const float* x         = (const float*)d_in[0];
    const int*   positions = (const int*)d_in[1];
    const float* wq        = (const float*)d_in[3];
    const float* wk        = (const float*)d_in[4];
    const float* wv        = (const float*)d_in[5];
    const float* wo        = (const float*)d_in[6];
    float* out = (float*)d_out;

    float  *qkv = nullptr;
    __half *xh = nullptr, *wh = nullptr, *attnh = nullptr, *qkh = nullptr, *vt = nullptr;
    cudaGetSymbolAddress((void**)&qkv,   g_qkv);
    cudaGetSymbolAddress((void**)&xh,    g_xh);
    cudaGetSymbolAddress((void**)&wh,    g_wh);
    cudaGetSymbolAddress((void**)&attnh, g_attnh);
    cudaGetSymbolAddress((void**)&qkh,   g_qkh);
    cudaGetSymbolAddress((void**)&vt,    g_vt);

    cudaFuncSetAttribute(qkv_gemm, cudaFuncAttributeMaxDynamicSharedMemorySize, GSMEM);
    cudaFuncSetAttribute(out_gemm, cudaFuncAttributeMaxDynamicSharedMemorySize, GSMEM);
    cudaFuncSetAttribute(attn_h,   cudaFuncAttributeMaxDynamicSharedMemorySize, ATT_SMEM);

    // fp32 -> fp16 converts (x + weights)
    const int cb = 256;
    conv_f2h<<<(TOKENS * HID / 4 + cb - 1) / cb, cb>>>(x,  xh,          TOKENS * HID / 4);
    conv_f2h<<<(4096 * HID / 4 + cb - 1) / cb, cb>>>(wq, wh + WQ_OFF, 4096 * HID / 4);
    conv_f2h<<<(1024 * HID / 4 + cb - 1) / cb, cb>>>(wk, wh + WK_OFF, 1024 * HID / 4);
    conv_f2h<<<(1024 * HID / 4 + cb - 1) / cb, cb>>>(wv, wh + WV_OFF, 1024 * HID / 4);
    conv_f2h<<<(4096 * HID / 4 + cb - 1) / cb, cb>>>(wo, wh + WO_OFF, 4096 * HID / 4);

    // QKV projection (fp16 HMMA)
    qkv_gemm<<<dim3(48, 32), 128, GSMEM>>>(xh, wh, qkv);

    // RoPE -> fp16 q|k; V transpose -> fp16 [d][pos]
    rope_h<<<(TOKENS * 40 * 64 + 255) / 256, 256>>>(qkv, positions, qkh);
    conv_vt<<<dim3(SEQ / 32, HDIM / 32, 4 * NKVH), 256>>>(qkv, vt);

    // Flash attention (fp16 HMMA, 2 CTAs/SM)
    attn_h<<<dim3(SEQ / 128, NHEADS, TOKENS / SEQ), 256, ATT_SMEM>>>(qkh, vt, attnh);

    // Output projection (fp16 HMMA)
    out_gemm<<<dim3(32, 32), 128, GSMEM>>>(attnh, wh, out);
}

// round 14
// speedup vs baseline: 2.6547x; 1.0062x over previous
#include <cuda_runtime.h>
#include <cuda_fp16.h>
#include <math.h>
#include <stdint.h>

#define TOKENS 4096
#define HID    4096
#define NHEADS 32
#define NKVH   8
#define HDIM   128
#define SEQ    1024
#define QKV_LD 6144   // q(4096) | k(1024) | v(1024)
#define QK_LD  5120   // fp16 rope'd: q(4096) | k(1024)

// Scratch (__device__ globals; allocation-free rule)
__device__ float  g_qkv[TOKENS * QKV_LD];          // fp32 qkv (gemm out, rope/vt in)
__device__ __half g_xh[TOKENS * HID];              // x in fp16
__device__ __half g_wh[10240 * HID];               // wq|wk|wv|wo in fp16
__device__ __half g_attnh[TOKENS * HID];           // attention output in fp16
__device__ __half g_qkh[TOKENS * QK_LD];           // rope'd q|k in fp16
__device__ __half g_vt[4 * NKVH * HDIM * SEQ];     // V transposed [b][kvh][d][pos]
#define WQ_OFF 0
#define WK_OFF (4096 * 4096)
#define WV_OFF (WK_OFF + 1024 * 4096)
#define WO_OFF (WV_OFF + 1024 * 4096)

// ---------------------------------------------------------------------------
// Helpers
// ---------------------------------------------------------------------------
__device__ __forceinline__ uint32_t smem_u32(const void* p) {
    uint32_t a;
    asm("{ .reg .u64 t; cvta.to.shared.u64 t, %1; cvt.u32.u64 %0, t; }"
        : "=r"(a) : "l"(p));
    return a;
}
__device__ __forceinline__ void mma_f16(float c[4],
    unsigned a0, unsigned a1, unsigned a2, unsigned a3,
    unsigned b0, unsigned b1) {
    asm volatile(
        "mma.sync.aligned.m16n8k16.row.col.f32.f16.f16.f32 "
        "{%0,%1,%2,%3}, {%4,%5,%6,%7}, {%8,%9}, {%0,%1,%2,%3};"
        : "+f"(c[0]), "+f"(c[1]), "+f"(c[2]), "+f"(c[3])
        : "r"(a0), "r"(a1), "r"(a2), "r"(a3), "r"(b0), "r"(b1));
}
__device__ __forceinline__ void cp16(uint32_t d, const void* s) {
    asm volatile("cp.async.cg.shared.global [%0], [%1], 16;" :: "r"(d), "l"(s));
}
#define CP_COMMIT() asm volatile("cp.async.commit_group;" ::: "memory")
#define CP_WAIT2()  asm volatile("cp.async.wait_group 2;" ::: "memory")

// packed half2 exp2 — ONE MUFU op for TWO exps (attention is MUFU-bound)
__device__ __forceinline__ unsigned h2ex2(unsigned x) {
    unsigned r;
    asm("ex2.approx.f16x2 %0, %1;" : "=r"(r) : "r"(x));
    return r;
}

// ---------------------------------------------------------------------------
// fp32 -> fp16 convert (vectorized)
// ---------------------------------------------------------------------------
__global__ void conv_f2h(const float* __restrict__ s, __half* __restrict__ d,
                         int n4) {
    int i = blockIdx.x * blockDim.x + threadIdx.x;
    if (i >= n4) return;
    float4 v = *(const float4*)(s + i * 4);
    __half2* dp = (__half2*)(d + i * 4);
    dp[0] = __floats2half2_rn(v.x, v.y);
    dp[1] = __floats2half2_rn(v.z, v.w);
}

// ---------------------------------------------------------------------------
// FP16 GEMM (round-11 proven): C[bm:bm+128, 0:128] = A @ Bt^T
// ---------------------------------------------------------------------------
#define RSW   20
#define ASTB  (128 * RSW * 4)            // 10240
#define STGB  (2 * ASTB)                 // 20480
#define KTH   (HID / 32)                 // 128
#define GSMEM (4 * STGB)                 // 81920

__device__ __forceinline__ void gemm128h(
    const __half* __restrict__ A, const __half* __restrict__ Bt,
    float* __restrict__ C, int ldc, int bm)
{
    extern __shared__ float smg[];

    const int tid  = threadIdx.x;
    const int wid  = tid >> 5;
    const int lane = tid & 31;
    const int g    = lane >> 2;
    const int t    = lane & 3;
    const int wm   = (wid & 1) * 64;
    const int wn   = (wid >> 1) * 64;
    const int lr   = tid >> 2;
    const int lc8  = (tid & 3) * 8;

    const uint32_t sb   = smem_u32(smg);
    const uint32_t adst = sb + (uint32_t)(lr * 80 + (tid & 3) * 16);
    const uint32_t bdst = adst + (uint32_t)ASTB;

    const __half* a0p = A  + (size_t)(bm + lr) * HID + lc8;
    const __half* b0p = Bt + (size_t)lr * HID + lc8;

#define ISSUE(S, KI) do { \
    const __half* a_ = a0p + (size_t)(KI) * 32; \
    const __half* b_ = b0p + (size_t)(KI) * 32; \
    const uint32_t so_ = (uint32_t)(S) * (uint32_t)STGB; \
    cp16(adst + so_,         a_); \
    cp16(adst + so_ + 2560u, a_ + (size_t)32 * HID); \
    cp16(adst + so_ + 5120u, a_ + (size_t)64 * HID); \
    cp16(adst + so_ + 7680u, a_ + (size_t)96 * HID); \
    cp16(bdst + so_,         b_); \
    cp16(bdst + so_ + 2560u, b_ + (size_t)32 * HID); \
    cp16(bdst + so_ + 5120u, b_ + (size_t)64 * HID); \
    cp16(bdst + so_ + 7680u, b_ + (size_t)96 * HID); \
} while (0)

    float acc[4][8][4];
#pragma unroll
    for (int i = 0; i < 4; i++)
#pragma unroll
        for (int j = 0; j < 8; j++)
#pragma unroll
            for (int r = 0; r < 4; r++) acc[i][j][r] = 0.f;

    ISSUE(0, 0); CP_COMMIT();
    ISSUE(1, 1); CP_COMMIT();
    ISSUE(2, 2); CP_COMMIT();

    for (int i = 0; i < KTH; i++) {
        CP_WAIT2();
        __syncthreads();

        if (i + 3 < KTH) ISSUE((i + 3) & 3, i + 3);
        CP_COMMIT();

        const uint32_t* as = (const uint32_t*)smg + (i & 3) * (STGB / 4);
        const uint32_t* bs = as + (ASTB / 4);
#pragma unroll
        for (int ks = 0; ks < 2; ks++) {
            const int kb = ks * 8;
            unsigned af[4][4], bf[8][2];
#pragma unroll
            for (int mi = 0; mi < 4; mi++) {
                const uint32_t* ap = as + (wm + mi * 16 + g) * RSW + kb + t;
                af[mi][0] = ap[0];
                af[mi][1] = ap[8 * RSW];
                af[mi][2] = ap[4];
                af[mi][3] = ap[8 * RSW + 4];
            }
#pragma unroll
            for (int ni = 0; ni < 8; ni++) {
                const uint32_t* bp = bs + (wn + ni * 8 + g) * RSW + kb + t;
                bf[ni][0] = bp[0];
                bf[ni][1] = bp[4];
            }
#pragma unroll
            for (int mi = 0; mi < 4; mi++)
#pragma unroll
                for (int ni = 0; ni < 8; ni++)
                    mma_f16(acc[mi][ni], af[mi][0], af[mi][1], af[mi][2], af[mi][3],
                            bf[ni][0], bf[ni][1]);
        }
    }
#undef ISSUE

#pragma unroll
    for (int mi = 0; mi < 4; mi++) {
#pragma unroll
        for (int ni = 0; ni < 8; ni++) {
            float* cp = C + (size_t)(bm + wm + mi * 16 + g) * ldc + wn + ni * 8 + 2 * t;
            *(float2*)cp             = make_float2(acc[mi][ni][0], acc[mi][ni][1]);
            *(float2*)(cp + 8 * ldc) = make_float2(acc[mi][ni][2], acc[mi][ni][3]);
        }
    }
}

__global__ __launch_bounds__(128, 2)
void qkv_gemm(const __half* __restrict__ xh, const __half* __restrict__ wh,
              float* __restrict__ qkv) {
    const int nt = blockIdx.x;
    const __half* B;
    if (nt < 32)      B = wh + WQ_OFF + (size_t)nt * 128 * HID;
    else if (nt < 40) B = wh + WK_OFF + (size_t)(nt - 32) * 128 * HID;
    else              B = wh + WV_OFF + (size_t)(nt - 40) * 128 * HID;
    gemm128h(xh, B, qkv + nt * 128, QKV_LD, blockIdx.y * 128);
}

__global__ __launch_bounds__(128, 2)
void out_gemm(const __half* __restrict__ ah, const __half* __restrict__ wh,
              float* __restrict__ C) {
    gemm128h(ah, wh + WO_OFF + (size_t)blockIdx.x * 128 * HID,
             C + blockIdx.x * 128, HID, blockIdx.y * 128);
}

// ---------------------------------------------------------------------------
// RoPE: read fp32 q/k from g_qkv, write fp16 into packed g_qkh.
// ---------------------------------------------------------------------------
__global__ void rope_h(const float* __restrict__ qkv,
                       const int* __restrict__ positions,
                       __half* __restrict__ qkh) {
    int idx = blockIdx.x * blockDim.x + threadIdx.x;
    const int total = TOKENS * (NHEADS + NKVH) * 64;
    if (idx >= total) return;
    int d = idx & 63;
    int rest = idx >> 6;
    int head = rest % (NHEADS + NKVH);
    int t = rest / (NHEADS + NKVH);

    int pos = positions[t];
    pos = pos < 0 ? 0 : (pos > SEQ - 1 ? SEQ - 1 : pos);

    const int off = (head < NHEADS) ? head * HDIM : HID + (head - NHEADS) * HDIM;
    const float* src = qkv + (size_t)t * QKV_LD + off;
    __half* dst = qkh + (size_t)t * QK_LD + off;
    float x1 = src[d];
    float x2 = src[d + 64];

    const float LC = 0.14391156831212875f;   // ln(10000)/64
    int j1 = d >> 1;
    float f1 = expf(-(float)j1 * LC);
    float f2 = expf(-(float)(j1 + 32) * LC);
    float p = (float)pos;
    float s1, c1, s2, c2;
    sincosf(p * f1, &s1, &c1);
    sincosf(p * f2, &s2, &c2);

    dst[d]      = __float2half(x1 * c1 - x2 * s1);
    dst[d + 64] = __float2half(x2 * c2 + x1 * s2);
}

// ---------------------------------------------------------------------------
// V transpose+convert: g_qkv v-region [tok][d] fp32 -> g_vt [b][kvh][d][pos] fp16.
// ---------------------------------------------------------------------------
__global__ void conv_vt(const float* __restrict__ qkv, __half* __restrict__ vt) {
    __shared__ float tile[32][33];
    const int bk = blockIdx.z;               // b*8 + kvh
    const int p0 = blockIdx.x * 32;
    const int d0 = blockIdx.y * 32;
    const int tx = threadIdx.x & 31;
    const int ty = threadIdx.x >> 5;         // 0..7
    const int b  = bk >> 3, kvh = bk & 7;

    const float* src = qkv + (size_t)(b * SEQ + p0) * QKV_LD + 5120 + kvh * HDIM + d0;
#pragma unroll
    for (int i = 0; i < 4; i++) {
        int r = ty + 8 * i;                   // pos within tile
        tile[r][tx] = src[(size_t)r * QKV_LD + tx];
    }
    __syncthreads();
    __half* dst = vt + ((size_t)bk * HDIM + d0) * SEQ + p0;
#pragma unroll
    for (int i = 0; i < 4; i++) {
        int r = ty + 8 * i;                   // d within tile
        dst[(size_t)r * SEQ + tx] = __float2half(tile[tx][r]);
    }
}

// ---------------------------------------------------------------------------
// FP16 tensor-core flash attention (causal, GQA), log2-domain softmax with
// packed ex2.approx.f16x2 (one MUFU for two exps — kernel is MUFU-bound).
// CTA: 128 q x 1 head, 256 thr = 8 warps, warp owns 16 full rows.
// ---------------------------------------------------------------------------
#define AQW 68
#define AKW 68
#define AVW 36
#define APW 36
#define ATTW (128 * AQW + 64 * AKW + 128 * AVW + 128 * APW)   // 22272 words
#define ATT_SMEM (ATTW * 4)                                    // 89088 B

__global__ __launch_bounds__(256, 2)
void attn_h(const __half* __restrict__ qkh, const __half* __restrict__ vt,
            __half* __restrict__ aout) {
    extern __shared__ uint32_t smw[];
    uint32_t* Qs = smw;
    uint32_t* Ks = Qs + 128 * AQW;
    uint32_t* Vs = Ks + 64 * AKW;
    uint32_t* Ps = Vs + 128 * AVW;

    const int qb = blockIdx.x;
    const int h  = blockIdx.y;
    const int b  = blockIdx.z;
    const int kvh = h >> 2;
    const int tid = threadIdx.x;
    const int wid = tid >> 5;
    const int lane = tid & 31;
    const int g = lane >> 2;
    const int t = lane & 3;
    const int wm = wid * 16;
    const int q0 = qb * 128;
    const size_t tok0 = (size_t)b * SEQ;

    // Load Q tile: 128 rows x 64 words = 16 uint4 chunks/row
    const __half* qbase = qkh + (tok0 + q0) * QK_LD + h * HDIM;
    for (int u = tid; u < 128 * 16; u += 256) {
        int r = u >> 4, c = u & 15;
        *(uint4*)(Qs + r * AQW + c * 4) =
            *(const uint4*)(qbase + (size_t)r * QK_LD + c * 8);
    }

    // m, l in LOG2 domain
    float m[2], l[2], o[16][4];
    m[0] = m[1] = -INFINITY;
    l[0] = l[1] = 0.f;
#pragma unroll
    for (int nj = 0; nj < 16; nj++)
#pragma unroll
        for (int r = 0; r < 4; r++) o[nj][r] = 0.f;

    const __half* kbase = qkh + tok0 * QK_LD + HID + kvh * HDIM;
    const __half* vtb   = vt + (size_t)(b * NKVH + kvh) * HDIM * SEQ;
    const int nkb = 2 * (qb + 1);

    for (int kb = 0; kb < nkb; kb++) {
        const int k0 = kb * 64;
        __syncthreads();
        for (int u = tid; u < 64 * 16; u += 256) {       // K: 16 chunks/row
            int r = u >> 4, c = u & 15;
            *(uint4*)(Ks + r * AKW + c * 4) =
                *(const uint4*)(kbase + (size_t)(k0 + r) * QK_LD + c * 8);
        }
        for (int u = tid; u < 128 * 8; u += 256) {       // Vt: 8 chunks/row
            int r = u >> 3, c = u & 7;
            *(uint4*)(Vs + r * AVW + c * 4) =
                *(const uint4*)(vtb + (size_t)r * SEQ + k0 + c * 8);
        }
        __syncthreads();

        if (k0 > q0 + wm + 15) continue;   // causal early-out

        // ---- S = Q K^T (fp16 k16, 8 slabs) ----
        float s[8][4];
#pragma unroll
        for (int ni = 0; ni < 8; ni++)
#pragma unroll
            for (int r = 0; r < 4; r++) s[ni][r] = 0.f;

#pragma unroll
        for (int kk = 0; kk < 8; kk++) {
            const int kc = kk * 8;
            const uint32_t* ap = Qs + (wm + g) * AQW + kc + t;
            unsigned a0 = ap[0], a1 = ap[8 * AQW], a2 = ap[4], a3 = ap[8 * AQW + 4];
#pragma unroll
            for (int ni = 0; ni < 8; ni++) {
                const uint32_t* bp = Ks + (ni * 8 + g) * AKW + kc + t;
                mma_f16(s[ni], a0, a1, a2, a3, bp[0], bp[4]);
            }
        }

        // ---- online softmax, log2 domain (rows wm+g, wm+g+8) ----
        const float sc2 = 0.12751742770800936f;  // log2(e)/sqrt(128)
#pragma unroll
        for (int h2 = 0; h2 < 2; h2++) {
            const int qpos = q0 + wm + g + h2 * 8;
            float rowm = -INFINITY;
#pragma unroll
            for (int ni = 0; ni < 8; ni++) {
#pragma unroll
                for (int cj = 0; cj < 2; cj++) {
                    float v = s[ni][h2 * 2 + cj] * sc2;
                    if (k0 + ni * 8 + 2 * t + cj > qpos) v = -INFINITY;
                    s[ni][h2 * 2 + cj] = v;
                    rowm = fmaxf(rowm, v);
                }
            }
            rowm = fmaxf(rowm, __shfl_xor_sync(0xffffffffu, rowm, 1));
            rowm = fmaxf(rowm, __shfl_xor_sync(0xffffffffu, rowm, 2));
            float nm  = fmaxf(m[h2], rowm);
            float nm2 = (nm == -INFINITY) ? 0.f : nm;    // NaN guard
            float corr = exp2f(m[h2] - nm2);
            float rs = 0.f;
            uint32_t* prow = Ps + (wm + g + h2 * 8) * APW;
#pragma unroll
            for (int ni = 0; ni < 8; ni++) {
                // packed f16x2 exp2: one MUFU for two probabilities
                __half2 qh = __floats2half2_rn(s[ni][h2 * 2]     - nm2,
                                               s[ni][h2 * 2 + 1] - nm2);
                unsigned ph = h2ex2(*(unsigned*)&qh);
                prow[ni * 4 + t] = ph;
                float2 pf = __half22float2(*(__half2*)&ph);
                rs += pf.x + pf.y;
            }
            rs += __shfl_xor_sync(0xffffffffu, rs, 1);
            rs += __shfl_xor_sync(0xffffffffu, rs, 2);
            l[h2] = l[h2] * corr + rs;
            m[h2] = nm;
#pragma unroll
            for (int nj = 0; nj < 16; nj++) {
                o[nj][h2 * 2]     *= corr;
                o[nj][h2 * 2 + 1] *= corr;
            }
        }
        __syncwarp();   // P visible within warp

        // ---- O += P V (fp16 k16, 4 slabs over 64 keys) ----
#pragma unroll
        for (int kk = 0; kk < 4; kk++) {
            const int kc = kk * 8;
            const uint32_t* ap = Ps + (wm + g) * APW + kc + t;
            unsigned a0 = ap[0], a1 = ap[8 * APW], a2 = ap[4], a3 = ap[8 * APW + 4];
#pragma unroll
            for (int nj = 0; nj < 16; nj++) {
                const uint32_t* bp = Vs + (nj * 8 + g) * AVW + kc + t;
                mma_f16(o[nj], a0, a1, a2, a3, bp[0], bp[4]);
            }
        }
    }

    // Epilogue: fp16 out (feeds out_gemm)
    __half* ob = aout + (tok0 + q0) * HID + h * HDIM;
#pragma unroll
    for (int h2 = 0; h2 < 2; h2++) {
        const float inv = 1.0f / l[h2];
        const int row = wm + g + h2 * 8;
#pragma unroll
        for (int nj = 0; nj < 16; nj++) {
            *(__half2*)(ob + (size_t)row * HID + nj * 8 + 2 * t) =
                __floats2half2_rn(o[nj][h2 * 2] * inv, o[nj][h2 * 2 + 1] * inv);
        }
    }
}

// ---------------------------------------------------------------------------
// Launch
// ---------------------------------------------------------------------------
extern "C" void kernel_launch(void* const* d_in, const int* in_sizes, int n_in,
                              void* d_out, int out_size) {
    const float* x         = (const float*)d_in[0];
    const int*   positions = (const int*)d_in[1];
    const float* wq        = (const float*)d_in[3];
    const float* wk        = (const float*)d_in[4];
    const float* wv        = (const float*)d_in[5];
    const float* wo        = (const float*)d_in[6];
    float* out = (float*)d_out;

    float  *qkv = nullptr;
    __half *xh = nullptr, *wh = nullptr, *attnh = nullptr, *qkh = nullptr, *vt = nullptr;
    cudaGetSymbolAddress((void**)&qkv,   g_qkv);
    cudaGetSymbolAddress((void**)&xh,    g_xh);
    cudaGetSymbolAddress((void**)&wh,    g_wh);
    cudaGetSymbolAddress((void**)&attnh, g_attnh);
    cudaGetSymbolAddress((void**)&qkh,   g_qkh);
    cudaGetSymbolAddress((void**)&vt,    g_vt);

    cudaFuncSetAttribute(qkv_gemm, cudaFuncAttributeMaxDynamicSharedMemorySize, GSMEM);
    cudaFuncSetAttribute(out_gemm, cudaFuncAttributeMaxDynamicSharedMemorySize, GSMEM);
    cudaFuncSetAttribute(attn_h,   cudaFuncAttributeMaxDynamicSharedMemorySize, ATT_SMEM);

    // fp32 -> fp16 converts (x + weights)
    const int cb = 256;
    conv_f2h<<<(TOKENS * HID / 4 + cb - 1) / cb, cb>>>(x,  xh,          TOKENS * HID / 4);
    conv_f2h<<<(4096 * HID / 4 + cb - 1) / cb, cb>>>(wq, wh + WQ_OFF, 4096 * HID / 4);
    conv_f2h<<<(1024 * HID / 4 + cb - 1) / cb, cb>>>(wk, wh + WK_OFF, 1024 * HID / 4);
    conv_f2h<<<(1024 * HID / 4 + cb - 1) / cb, cb>>>(wv, wh + WV_OFF, 1024 * HID / 4);
    conv_f2h<<<(4096 * HID / 4 + cb - 1) / cb, cb>>>(wo, wh + WO_OFF, 4096 * HID / 4);

    // QKV projection (fp16 HMMA)
    qkv_gemm<<<dim3(48, 32), 128, GSMEM>>>(xh, wh, qkv);

    // RoPE -> fp16 q|k; V transpose -> fp16 [d][pos]
    rope_h<<<(TOKENS * 40 * 64 + 255) / 256, 256>>>(qkv, positions, qkh);
    conv_vt<<<dim3(SEQ / 32, HDIM / 32, 4 * NKVH), 256>>>(qkv, vt);

    // Flash attention (fp16 HMMA + f16x2 exp2, 2 CTAs/SM)
    attn_h<<<dim3(SEQ / 128, NHEADS, TOKENS / SEQ), 256, ATT_SMEM>>>(qkh, vt, attnh);

    // Output projection (fp16 HMMA)
    out_gemm<<<dim3(32, 32), 128, GSMEM>>>(attnh, wh, out);
}

// round 15
// speedup vs baseline: 2.7232x; 1.0258x over previous
#include <cuda_runtime.h>
#include <cuda_fp16.h>
#include <math.h>
#include <stdint.h>

#define TOKENS 4096
#define HID    4096
#define NHEADS 32
#define NKVH   8
#define HDIM   128
#define SEQ    1024
#define QKV_LD 6144   // q(4096) | k(1024) | v(1024)
#define QK_LD  5120   // fp16 rope'd: q(4096) | k(1024)

// Scratch (__device__ globals; allocation-free rule)
__device__ float  g_qkv[TOKENS * QKV_LD];          // fp32 qkv (gemm out, rope/vt in)
__device__ __half g_xh[TOKENS * HID];              // x in fp16
__device__ __half g_wh[10240 * HID];               // wq|wk|wv|wo in fp16
__device__ __half g_attnh[TOKENS * HID];           // attention output in fp16
__device__ __half g_qkh[TOKENS * QK_LD];           // rope'd q|k in fp16
__device__ __half g_vt[4 * NKVH * HDIM * SEQ];     // V transposed [b][kvh][d][pos]
#define WQ_OFF 0
#define WK_OFF (4096 * 4096)
#define WV_OFF (WK_OFF + 1024 * 4096)
#define WO_OFF (WV_OFF + 1024 * 4096)

// ---------------------------------------------------------------------------
// Helpers
// ---------------------------------------------------------------------------
__device__ __forceinline__ uint32_t smem_u32(const void* p) {
    uint32_t a;
    asm("{ .reg .u64 t; cvta.to.shared.u64 t, %1; cvt.u32.u64 %0, t; }"
        : "=r"(a) : "l"(p));
    return a;
}
__device__ __forceinline__ void mma_f16(float c[4],
    unsigned a0, unsigned a1, unsigned a2, unsigned a3,
    unsigned b0, unsigned b1) {
    asm volatile(
        "mma.sync.aligned.m16n8k16.row.col.f32.f16.f16.f32 "
        "{%0,%1,%2,%3}, {%4,%5,%6,%7}, {%8,%9}, {%0,%1,%2,%3};"
        : "+f"(c[0]), "+f"(c[1]), "+f"(c[2]), "+f"(c[3])
        : "r"(a0), "r"(a1), "r"(a2), "r"(a3), "r"(b0), "r"(b1));
}
__device__ __forceinline__ void cp16(uint32_t d, const void* s) {
    asm volatile("cp.async.cg.shared.global [%0], [%1], 16;" :: "r"(d), "l"(s));
}
#define CP_COMMIT() asm volatile("cp.async.commit_group;" ::: "memory")
#define CP_WAIT2()  asm volatile("cp.async.wait_group 2;" ::: "memory")
#define CP_WAIT1()  asm volatile("cp.async.wait_group 1;" ::: "memory")

// packed half2 exp2 — one MUFU op for two exps
__device__ __forceinline__ unsigned h2ex2(unsigned x) {
    unsigned r;
    asm("ex2.approx.f16x2 %0, %1;" : "=r"(r) : "r"(x));
    return r;
}

// ---------------------------------------------------------------------------
// fp32 -> fp16 convert (vectorized)
// ---------------------------------------------------------------------------
__global__ void conv_f2h(const float* __restrict__ s, __half* __restrict__ d,
                         int n4) {
    int i = blockIdx.x * blockDim.x + threadIdx.x;
    if (i >= n4) return;
    float4 v = *(const float4*)(s + i * 4);
    __half2* dp = (__half2*)(d + i * 4);
    dp[0] = __floats2half2_rn(v.x, v.y);
    dp[1] = __floats2half2_rn(v.z, v.w);
}

// ---------------------------------------------------------------------------
// FP16 GEMM (round-11 proven): C[bm:bm+128, 0:128] = A @ Bt^T
// ---------------------------------------------------------------------------
#define RSW   20
#define ASTB  (128 * RSW * 4)            // 10240
#define STGB  (2 * ASTB)                 // 20480
#define KTH   (HID / 32)                 // 128
#define GSMEM (4 * STGB)                 // 81920

__device__ __forceinline__ void gemm128h(
    const __half* __restrict__ A, const __half* __restrict__ Bt,
    float* __restrict__ C, int ldc, int bm)
{
    extern __shared__ float smg[];

    const int tid  = threadIdx.x;
    const int wid  = tid >> 5;
    const int lane = tid & 31;
    const int g    = lane >> 2;
    const int t    = lane & 3;
    const int wm   = (wid & 1) * 64;
    const int wn   = (wid >> 1) * 64;
    const int lr   = tid >> 2;
    const int lc8  = (tid & 3) * 8;

    const uint32_t sb   = smem_u32(smg);
    const uint32_t adst = sb + (uint32_t)(lr * 80 + (tid & 3) * 16);
    const uint32_t bdst = adst + (uint32_t)ASTB;

    const __half* a0p = A  + (size_t)(bm + lr) * HID + lc8;
    const __half* b0p = Bt + (size_t)lr * HID + lc8;

#define ISSUE(S, KI) do { \
    const __half* a_ = a0p + (size_t)(KI) * 32; \
    const __half* b_ = b0p + (size_t)(KI) * 32; \
    const uint32_t so_ = (uint32_t)(S) * (uint32_t)STGB; \
    cp16(adst + so_,         a_); \
    cp16(adst + so_ + 2560u, a_ + (size_t)32 * HID); \
    cp16(adst + so_ + 5120u, a_ + (size_t)64 * HID); \
    cp16(adst + so_ + 7680u, a_ + (size_t)96 * HID); \
    cp16(bdst + so_,         b_); \
    cp16(bdst + so_ + 2560u, b_ + (size_t)32 * HID); \
    cp16(bdst + so_ + 5120u, b_ + (size_t)64 * HID); \
    cp16(bdst + so_ + 7680u, b_ + (size_t)96 * HID); \
} while (0)

    float acc[4][8][4];
#pragma unroll
    for (int i = 0; i < 4; i++)
#pragma unroll
        for (int j = 0; j < 8; j++)
#pragma unroll
            for (int r = 0; r < 4; r++) acc[i][j][r] = 0.f;

    ISSUE(0, 0); CP_COMMIT();
    ISSUE(1, 1); CP_COMMIT();
    ISSUE(2, 2); CP_COMMIT();

    for (int i = 0; i < KTH; i++) {
        CP_WAIT2();
        __syncthreads();

        if (i + 3 < KTH) ISSUE((i + 3) & 3, i + 3);
        CP_COMMIT();

        const uint32_t* as = (const uint32_t*)smg + (i & 3) * (STGB / 4);
        const uint32_t* bs = as + (ASTB / 4);
#pragma unroll
        for (int ks = 0; ks < 2; ks++) {
            const int kb = ks * 8;
            unsigned af[4][4], bf[8][2];
#pragma unroll
            for (int mi = 0; mi < 4; mi++) {
                const uint32_t* ap = as + (wm + mi * 16 + g) * RSW + kb + t;
                af[mi][0] = ap[0];
                af[mi][1] = ap[8 * RSW];
                af[mi][2] = ap[4];
                af[mi][3] = ap[8 * RSW + 4];
            }
#pragma unroll
            for (int ni = 0; ni < 8; ni++) {
                const uint32_t* bp = bs + (wn + ni * 8 + g) * RSW + kb + t;
                bf[ni][0] = bp[0];
                bf[ni][1] = bp[4];
            }
#pragma unroll
            for (int mi = 0; mi < 4; mi++)
#pragma unroll
                for (int ni = 0; ni < 8; ni++)
                    mma_f16(acc[mi][ni], af[mi][0], af[mi][1], af[mi][2], af[mi][3],
                            bf[ni][0], bf[ni][1]);
        }
    }
#undef ISSUE

#pragma unroll
    for (int mi = 0; mi < 4; mi++) {
#pragma unroll
        for (int ni = 0; ni < 8; ni++) {
            float* cp = C + (size_t)(bm + wm + mi * 16 + g) * ldc + wn + ni * 8 + 2 * t;
            *(float2*)cp             = make_float2(acc[mi][ni][0], acc[mi][ni][1]);
            *(float2*)(cp + 8 * ldc) = make_float2(acc[mi][ni][2], acc[mi][ni][3]);
        }
    }
}

__global__ __launch_bounds__(128, 2)
void qkv_gemm(const __half* __restrict__ xh, const __half* __restrict__ wh,
              float* __restrict__ qkv) {
    const int nt = blockIdx.x;
    const __half* B;
    if (nt < 32)      B = wh + WQ_OFF + (size_t)nt * 128 * HID;
    else if (nt < 40) B = wh + WK_OFF + (size_t)(nt - 32) * 128 * HID;
    else              B = wh + WV_OFF + (size_t)(nt - 40) * 128 * HID;
    gemm128h(xh, B, qkv + nt * 128, QKV_LD, blockIdx.y * 128);
}

__global__ __launch_bounds__(128, 2)
void out_gemm(const __half* __restrict__ ah, const __half* __restrict__ wh,
              float* __restrict__ C) {
    gemm128h(ah, wh + WO_OFF + (size_t)blockIdx.x * 128 * HID,
             C + blockIdx.x * 128, HID, blockIdx.y * 128);
}

// ---------------------------------------------------------------------------
// RoPE: read fp32 q/k from g_qkv, write fp16 into packed g_qkh.
// ---------------------------------------------------------------------------
__global__ void rope_h(const float* __restrict__ qkv,
                       const int* __restrict__ positions,
                       __half* __restrict__ qkh) {
    int idx = blockIdx.x * blockDim.x + threadIdx.x;
    const int total = TOKENS * (NHEADS + NKVH) * 64;
    if (idx >= total) return;
    int d = idx & 63;
    int rest = idx >> 6;
    int head = rest % (NHEADS + NKVH);
    int t = rest / (NHEADS + NKVH);

    int pos = positions[t];
    pos = pos < 0 ? 0 : (pos > SEQ - 1 ? SEQ - 1 : pos);

    const int off = (head < NHEADS) ? head * HDIM : HID + (head - NHEADS) * HDIM;
    const float* src = qkv + (size_t)t * QKV_LD + off;
    __half* dst = qkh + (size_t)t * QK_LD + off;
    float x1 = src[d];
    float x2 = src[d + 64];

    const float LC = 0.14391156831212875f;   // ln(10000)/64
    int j1 = d >> 1;
    float f1 = expf(-(float)j1 * LC);
    float f2 = expf(-(float)(j1 + 32) * LC);
    float p = (float)pos;
    float s1, c1, s2, c2;
    sincosf(p * f1, &s1, &c1);
    sincosf(p * f2, &s2, &c2);

    dst[d]      = __float2half(x1 * c1 - x2 * s1);
    dst[d + 64] = __float2half(x2 * c2 + x1 * s2);
}

// ---------------------------------------------------------------------------
// V transpose+convert: g_qkv v-region [tok][d] fp32 -> g_vt [b][kvh][d][pos] fp16.
// ---------------------------------------------------------------------------
__global__ void conv_vt(const float* __restrict__ qkv, __half* __restrict__ vt) {
    __shared__ float tile[32][33];
    const int bk = blockIdx.z;               // b*8 + kvh
    const int p0 = blockIdx.x * 32;
    const int d0 = blockIdx.y * 32;
    const int tx = threadIdx.x & 31;
    const int ty = threadIdx.x >> 5;         // 0..7
    const int b  = bk >> 3, kvh = bk & 7;

    const float* src = qkv + (size_t)(b * SEQ + p0) * QKV_LD + 5120 + kvh * HDIM + d0;
#pragma unroll
    for (int i = 0; i < 4; i++) {
        int r = ty + 8 * i;                   // pos within tile
        tile[r][tx] = src[(size_t)r * QKV_LD + tx];
    }
    __syncthreads();
    __half* dst = vt + ((size_t)bk * HDIM + d0) * SEQ + p0;
#pragma unroll
    for (int i = 0; i < 4; i++) {
        int r = ty + 8 * i;                   // d within tile
        dst[(size_t)r * SEQ + tx] = __float2half(tile[tx][r]);
    }
}

// ---------------------------------------------------------------------------
// FP16 tensor-core flash attention (causal, GQA), log2-domain f16x2 softmax.
// NEW: XOR-swizzled pad-free smem (col' = col ^ 4*(row&7)) + cp.async
// double-buffered K/V pipeline issued 2 tiles ahead. 112 KB smem, 2 CTAs/SM.
// Fragment-gather bank math: banks = (col^4g) -> low2=t, mid=g^const: all 32
// distinct for every gather pattern. "+4 cols" partner is idx^4 (bit2 of col
// is 0 pre-swizzle: kc%8==0, t<4).
// ---------------------------------------------------------------------------
#define QW64  64
#define KW64  64
#define VW32  32
#define PW32  32
#define Q_OFF 0
#define K_OFF (128 * QW64)                 // 8192
#define V_OFF (K_OFF + 2 * 64 * KW64)      // 16384
#define P_OFF (V_OFF + 2 * 128 * VW32)     // 24576
#define ATTW  (P_OFF + 128 * PW32)         // 28672 words
#define ATT_SMEM (ATTW * 4)                // 114688 B

__global__ __launch_bounds__(256, 2)
void attn_h(const __half* __restrict__ qkh, const __half* __restrict__ vt,
            __half* __restrict__ aout) {
    extern __shared__ uint32_t smw[];
    uint32_t* Qs = smw + Q_OFF;
    uint32_t* Ks = smw + K_OFF;            // 2 x 4096 words
    uint32_t* Vs = smw + V_OFF;            // 2 x 4096 words
    uint32_t* Ps = smw + P_OFF;

    const int qb = 7 - blockIdx.x;         // long CTAs first (tail balance)
    const int h  = blockIdx.y;
    const int b  = blockIdx.z;
    const int kvh = h >> 2;
    const int tid = threadIdx.x;
    const int wid = tid >> 5;
    const int lane = tid & 31;
    const int g = lane >> 2;
    const int t = lane & 3;
    const int swg = g << 2;
    const int wm = wid * 16;
    const int q0 = qb * 128;
    const size_t tok0 = (size_t)b * SEQ;

    const __half* qbase = qkh + (tok0 + q0) * QK_LD + h * HDIM;
    const __half* kbase = qkh + tok0 * QK_LD + HID + kvh * HDIM;
    const __half* vtb   = vt + (size_t)(b * NKVH + kvh) * HDIM * SEQ;
    const int nkb = 2 * (qb + 1);          // >= 2 always

    const uint32_t sb = smem_u32(smw);

    // cp.async issue of one K/V tile into buffer S (8 x 16B per thread)
#define ISSUE_KV(S, KB) do { \
    const int k0_ = (KB) * 64; \
    const uint32_t kb_ = sb + (uint32_t)(K_OFF + (S) * 4096) * 4u; \
    const uint32_t vb_ = sb + (uint32_t)(V_OFF + (S) * 4096) * 4u; \
    _Pragma("unroll") \
    for (int i_ = 0; i_ < 4; i_++) { \
        int u_ = tid + 256 * i_; \
        int r_ = u_ >> 4, c4_ = (u_ & 15) * 4; \
        cp16(kb_ + (uint32_t)(r_ * KW64 + (c4_ ^ ((r_ & 7) << 2))) * 4u, \
             kbase + (size_t)(k0_ + r_) * QK_LD + c4_ * 2); \
    } \
    _Pragma("unroll") \
    for (int i_ = 0; i_ < 4; i_++) { \
        int u_ = tid + 256 * i_; \
        int r_ = u_ >> 3, c4_ = (u_ & 7) * 4; \
        cp16(vb_ + (uint32_t)(r_ * VW32 + (c4_ ^ ((r_ & 7) << 2))) * 4u, \
             vtb + (size_t)r_ * SEQ + k0_ + c4_ * 2); \
    } \
} while (0)

    // Prologue: 2 tiles in flight
    ISSUE_KV(0, 0); CP_COMMIT();
    ISSUE_KV(1, 1); CP_COMMIT();

    // Q tile load (plain; overlaps with the async copies above)
    for (int u = tid; u < 128 * 16; u += 256) {
        int r = u >> 4, c4 = (u & 15) * 4;
        *(uint4*)(Qs + r * QW64 + (c4 ^ ((r & 7) << 2))) =
            *(const uint4*)(qbase + (size_t)r * QK_LD + c4 * 2);
    }

    // m, l in LOG2 domain
    float m[2], l[2], o[16][4];
    m[0] = m[1] = -INFINITY;
    l[0] = l[1] = 0.f;
#pragma unroll
    for (int nj = 0; nj < 16; nj++)
#pragma unroll
        for (int r = 0; r < 4; r++) o[nj][r] = 0.f;

    for (int kb = 0; kb < nkb; kb++) {
        const int k0 = kb * 64;
        CP_WAIT1();            // tile kb complete (kb+1 may still be pending)
        __syncthreads();       // all threads' copies visible

        if (k0 <= q0 + wm + 15) {   // causal: warp has live rows
            const uint32_t* Kb = Ks + (kb & 1) * 4096;
            const uint32_t* Vb = Vs + (kb & 1) * 4096;

            // ---- S = Q K^T (fp16 k16, 8 slabs) ----
            float s[8][4];
#pragma unroll
            for (int ni = 0; ni < 8; ni++)
#pragma unroll
                for (int r = 0; r < 4; r++) s[ni][r] = 0.f;

#pragma unroll
            for (int kk = 0; kk < 8; kk++) {
                const int col = (kk * 8 + t) ^ swg;
                const int qi = (wm + g) * QW64 + col;
                unsigned a0 = Qs[qi],      a1 = Qs[qi + 8 * QW64];
                unsigned a2 = Qs[qi ^ 4],  a3 = Qs[(qi ^ 4) + 8 * QW64];
#pragma unroll
                for (int ni = 0; ni < 8; ni++) {
                    const int ki = (ni * 8 + g) * KW64 + col;
                    mma_f16(s[ni], a0, a1, a2, a3, Kb[ki], Kb[ki ^ 4]);
                }
            }

            // ---- online softmax, log2 domain ----
            const float sc2 = 0.12751742770800936f;  // log2(e)/sqrt(128)
#pragma unroll
            for (int h2 = 0; h2 < 2; h2++) {
                const int qpos = q0 + wm + g + h2 * 8;
                float rowm = -INFINITY;
#pragma unroll
                for (int ni = 0; ni < 8; ni++) {
#pragma unroll
                    for (int cj = 0; cj < 2; cj++) {
                        float v = s[ni][h2 * 2 + cj] * sc2;
                        if (k0 + ni * 8 + 2 * t + cj > qpos) v = -INFINITY;
                        s[ni][h2 * 2 + cj] = v;
                        rowm = fmaxf(rowm, v);
                    }
                }
                rowm = fmaxf(rowm, __shfl_xor_sync(0xffffffffu, rowm, 1));
                rowm = fmaxf(rowm, __shfl_xor_sync(0xffffffffu, rowm, 2));
                float nm  = fmaxf(m[h2], rowm);
                float nm2 = (nm == -INFINITY) ? 0.f : nm;    // NaN guard
                float corr = exp2f(m[h2] - nm2);
                float rs = 0.f;
                const int prow = (wm + g + h2 * 8) * PW32;   // swizzle = swg
#pragma unroll
                for (int ni = 0; ni < 8; ni++) {
                    __half2 qh = __floats2half2_rn(s[ni][h2 * 2]     - nm2,
                                                   s[ni][h2 * 2 + 1] - nm2);
                    unsigned ph = h2ex2(*(unsigned*)&qh);
                    Ps[prow + ((ni * 4 + t) ^ swg)] = ph;
                    float2 pf = __half22float2(*(__half2*)&ph);
                    rs += pf.x + pf.y;
                }
                rs += __shfl_xor_sync(0xffffffffu, rs, 1);
                rs += __shfl_xor_sync(0xffffffffu, rs, 2);
                l[h2] = l[h2] * corr + rs;
                m[h2] = nm;
#pragma unroll
                for (int nj = 0; nj < 16; nj++) {
                    o[nj][h2 * 2]     *= corr;
                    o[nj][h2 * 2 + 1] *= corr;
                }
            }
            __syncwarp();   // P visible within warp

            // ---- O += P V (fp16 k16, 4 slabs over 64 keys) ----
#pragma unroll
            for (int kk = 0; kk < 4; kk++) {
                const int col = (kk * 8 + t) ^ swg;
                const int pi = (wm + g) * PW32 + col;
                unsigned a0 = Ps[pi],      a1 = Ps[pi + 8 * PW32];
                unsigned a2 = Ps[pi ^ 4],  a3 = Ps[(pi ^ 4) + 8 * PW32];
#pragma unroll
                for (int nj = 0; nj < 16; nj++) {
                    const int vi = (nj * 8 + g) * VW32 + col;
                    mma_f16(o[nj], a0, a1, a2, a3, Vb[vi], Vb[vi ^ 4]);
                }
            }
        }

        __syncthreads();       // all warps done with buf (kb&1) before reuse
        if (kb + 2 < nkb) ISSUE_KV(kb & 1, kb + 2);
        CP_COMMIT();           // uniform group count (possibly empty)
    }
#undef ISSUE_KV

    // Epilogue: fp16 out (feeds out_gemm)
    __half* ob = aout + (tok0 + q0) * HID + h * HDIM;
#pragma unroll
    for (int h2 = 0; h2 < 2; h2++) {
        const float inv = 1.0f / l[h2];
        const int row = wm + g + h2 * 8;
#pragma unroll
        for (int nj = 0; nj < 16; nj++) {
            *(__half2*)(ob + (size_t)row * HID + nj * 8 + 2 * t) =
                __floats2half2_rn(o[nj][h2 * 2] * inv, o[nj][h2 * 2 + 1] * inv);
        }
    }
}

// ---------------------------------------------------------------------------
// Launch
// ---------------------------------------------------------------------------
extern "C" void kernel_launch(void* const* d_in, const int* in_sizes, int n_in,
                              void* d_out, int out_size) {
    const float* x         = (const float*)d_in[0];
    const int*   positions = (const int*)d_in[1];
    const float* wq        = (const float*)d_in[3];
    const float* wk        = (const float*)d_in[4];
    const float* wv        = (const float*)d_in[5];
    const float* wo        = (const float*)d_in[6];
    float* out = (float*)d_out;

    float  *qkv = nullptr;
    __half *xh = nullptr, *wh = nullptr, *attnh = nullptr, *qkh = nullptr, *vt = nullptr;
    cudaGetSymbolAddress((void**)&qkv,   g_qkv);
    cudaGetSymbolAddress((void**)&xh,    g_xh);
    cudaGetSymbolAddress((void**)&wh,    g_wh);
    cudaGetSymbolAddress((void**)&attnh, g_attnh);
    cudaGetSymbolAddress((void**)&qkh,   g_qkh);
    cudaGetSymbolAddress((void**)&vt,    g_vt);

    cudaFuncSetAttribute(qkv_gemm, cudaFuncAttributeMaxDynamicSharedMemorySize, GSMEM);
    cudaFuncSetAttribute(out_gemm, cudaFuncAttributeMaxDynamicSharedMemorySize, GSMEM);
    cudaFuncSetAttribute(attn_h,   cudaFuncAttributeMaxDynamicSharedMemorySize, ATT_SMEM);

    // fp32 -> fp16 converts (x + weights)
    const int cb = 256;
    conv_f2h<<<(TOKENS * HID / 4 + cb - 1) / cb, cb>>>(x,  xh,          TOKENS * HID / 4);
    conv_f2h<<<(4096 * HID / 4 + cb - 1) / cb, cb>>>(wq, wh + WQ_OFF, 4096 * HID / 4);
    conv_f2h<<<(1024 * HID / 4 + cb - 1) / cb, cb>>>(wk, wh + WK_OFF, 1024 * HID / 4);
    conv_f2h<<<(1024 * HID / 4 + cb - 1) / cb, cb>>>(wv, wh + WV_OFF, 1024 * HID / 4);
    conv_f2h<<<(4096 * HID / 4 + cb - 1) / cb, cb>>>(wo, wh + WO_OFF, 4096 * HID / 4);

    // QKV projection (fp16 HMMA)
    qkv_gemm<<<dim3(48, 32), 128, GSMEM>>>(xh, wh, qkv);

    // RoPE -> fp16 q|k; V transpose -> fp16 [d][pos]
    rope_h<<<(TOKENS * 40 * 64 + 255) / 256, 256>>>(qkv, positions, qkh);
    conv_vt<<<dim3(SEQ / 32, HDIM / 32, 4 * NKVH), 256>>>(qkv, vt);

    // Flash attention (fp16 HMMA, cp.async K/V pipeline, 2 CTAs/SM)
    attn_h<<<dim3(SEQ / 128, NHEADS, TOKENS / SEQ), 256, ATT_SMEM>>>(qkh, vt, attnh);

    // Output projection (fp16 HMMA)
    out_gemm<<<dim3(32, 32), 128, GSMEM>>>(attnh, wh, out);
}